// round 14
// baseline (speedup 1.0000x reference)
#include <cuda_runtime.h>
#include <math.h>
#include <stdint.h>

// ---------------- problem constants -----------------------------------------
#define NNODE 19200
#define NEDGE 230400
#define NGRAPH 128
#define LATENT 256
#define FEAT 64
#define HEADS 4
#define POS 180
#define DMODEL 256       // HEADS * FEAT
#define ETOT (NEDGE + NNODE)
#define NBLK 75          // NNODE / 256
#define EBLK 900         // NEDGE / 256
#define WBLK 2400        // NNODE / 8 (8 warps per block)
#define FB 64            // nodes per k_final block

// ---------------- static device scratch --------------------------------------
__device__ __align__(16) float g_bufA[NNODE * DMODEL];
__device__ __align__(16) float g_bufB[NNODE * DMODEL];
__device__ __align__(16) float g_as[NNODE * HEADS];
__device__ __align__(16) float g_ad[NNODE * HEADS];
__device__ __align__(16) float g_ex[ETOT * HEADS];
__device__ __align__(16) float g_pg[NGRAPH * DMODEL];
__device__ __align__(16) float g_maxS[3][4];   // per-layer global aS max (slots)
__device__ int g_starts[NGRAPH];
__device__ int g_deg[NNODE];      // zero at load; re-zeroed each replay in k_mid
__device__ int g_rowptr[NNODE + 1];
__device__ int g_cursor[NNODE];
__device__ int g_csrc[ETOT];

__device__ __forceinline__ void atomicMaxF(float* a, float v) {
    if (v >= 0.0f) atomicMax((int*)a, __float_as_int(v));
    else           atomicMin((unsigned int*)a, __float_as_uint(v));
}

// ---------------- fused prologue: x0pg | starts | hist -------------------------
__global__ void k_pro(const float* __restrict__ z, const float* __restrict__ W0,
                      const float* __restrict__ b0, const float* __restrict__ W1,
                      float* __restrict__ pg, const int* __restrict__ batch,
                      int* __restrict__ starts, int* __restrict__ deg,
                      const int* __restrict__ dst) {
    cudaGridDependencySynchronize();
    int b = blockIdx.x;
    int t = threadIdx.x;
    if (b < NGRAPH) {
        __shared__ float xs[FEAT];
        if (t < FEAT) {
            float acc = b0[t];
            const float* zr = z + b * LATENT;
            #pragma unroll 4
            for (int k = 0; k < LATENT; k++) acc += zr[k] * W0[k * FEAT + t];
            xs[t] = acc > 0.0f ? acc : 0.0f;
        }
        __syncthreads();
        float a = 0.0f;
        #pragma unroll
        for (int k = 0; k < FEAT; k++) a += xs[k] * W1[k * DMODEL + t];
        pg[b * DMODEL + t] = a;
    } else if (b < NGRAPH + NBLK) {
        int i = (b - NGRAPH) * 256 + t;
        int bb = batch[i];
        if (i == 0 || batch[i - 1] != bb) starts[bb] = i;
    } else {
        int e = (b - NGRAPH - NBLK) * 256 + t;
        atomicAdd(&deg[dst[e]], 1);
    }
}

// ---------------- CSR: prefix + local scan + self-loop fill + maxS init --------
__global__ void k_fill2(const int* __restrict__ deg, int* __restrict__ rowptr,
                        int* __restrict__ cursor, int* __restrict__ csrc,
                        float* __restrict__ maxS) {
    cudaGridDependencySynchronize();
    __shared__ int red[256];
    __shared__ int s[256];
    int t = threadIdx.x;
    int b = blockIdx.x;
    if (b == 0 && t < 12) maxS[t] = __int_as_float(0xff800000);  // -inf, 3 slots
    int lim = b * 256;
    int sum = 0;
    for (int i = t; i < lim; i += 256) sum += deg[i] + 1;   // +1 self loop
    red[t] = sum;
    __syncthreads();
    for (int off = 128; off > 0; off >>= 1) {
        if (t < off) red[t] += red[t + off];
        __syncthreads();
    }
    int node = lim + t;
    int d = deg[node] + 1;
    s[t] = d;
    __syncthreads();
    for (int off = 1; off < 256; off <<= 1) {
        int u = (t >= off) ? s[t - off] : 0;
        __syncthreads();
        s[t] += u;
        __syncthreads();
    }
    int r = red[0] + s[t] - d;
    rowptr[node] = r;
    csrc[r] = node;                           // self loop first
    cursor[node] = r + 1;
    if (node == NNODE - 1) rowptr[NNODE] = red[0] + s[t];
}

// ---------------- fused: h1+attn | CSR scatter | deg re-zero --------------------
__global__ void k_mid(const float* __restrict__ pg, const float* __restrict__ W1,
                      const int* __restrict__ batch, const int* __restrict__ starts,
                      const float* __restrict__ attS, const float* __restrict__ attD,
                      float* __restrict__ H, float* __restrict__ aS,
                      float* __restrict__ aD,
                      const int* __restrict__ src, const int* __restrict__ dst,
                      int* __restrict__ cursor, int* __restrict__ csrc,
                      int* __restrict__ deg, float* __restrict__ maxS) {
    cudaGridDependencySynchronize();
    int b = blockIdx.x;
    int tid = threadIdx.x;
    if (b >= WBLK + EBLK) {
        deg[(b - WBLK - EBLK) * 256 + tid] = 0;
        return;
    }
    if (b >= WBLK) {
        int e = (b - WBLK) * 256 + tid;
        int p = atomicAdd(&cursor[dst[e]], 1);
        csrc[p] = src[e];
        return;
    }
    __shared__ float sS[DMODEL], sD[DMODEL];
    __shared__ float sMax[4];
    if (tid < DMODEL) { sS[tid] = attS[tid]; sD[tid] = attD[tid]; }
    if (tid < 4) sMax[tid] = __int_as_float(0xff800000);
    __syncthreads();
    int node = b * 8 + (tid >> 5);
    int lane = tid & 31;
    int g = batch[node];
    int order = node - starts[g];
    int c0 = lane * 8;
    const float4* pgr = (const float4*)(pg + g * DMODEL + c0);
    const float4* w1r = (const float4*)(W1 + (FEAT + order) * DMODEL + c0);
    float4 p0 = pgr[0], p1 = pgr[1];
    float4 w0 = w1r[0], w1v = w1r[1];
    float h[8];
    h[0] = p0.x + w0.x; h[1] = p0.y + w0.y; h[2] = p0.z + w0.z; h[3] = p0.w + w0.w;
    h[4] = p1.x + w1v.x; h[5] = p1.y + w1v.y; h[6] = p1.z + w1v.z; h[7] = p1.w + w1v.w;
    float* hr = H + node * DMODEL + c0;
    *(float4*)hr       = make_float4(h[0], h[1], h[2], h[3]);
    *(float4*)(hr + 4) = make_float4(h[4], h[5], h[6], h[7]);
    float pS = 0.0f, pD = 0.0f;
    #pragma unroll
    for (int j = 0; j < 8; j++) { pS += h[j] * sS[c0 + j]; pD += h[j] * sD[c0 + j]; }
    pS += __shfl_xor_sync(0xffffffffu, pS, 1);
    pS += __shfl_xor_sync(0xffffffffu, pS, 2);
    pS += __shfl_xor_sync(0xffffffffu, pS, 4);
    pD += __shfl_xor_sync(0xffffffffu, pD, 1);
    pD += __shfl_xor_sync(0xffffffffu, pD, 2);
    pD += __shfl_xor_sync(0xffffffffu, pD, 4);
    if ((lane & 7) == 0) {
        int hd = lane >> 3;
        aS[node * 4 + hd] = pS;
        aD[node * 4 + hd] = pD;
        atomicMaxF(&sMax[hd], pS);
    }
    __syncthreads();
    if (tid < 4) atomicMaxF(&maxS[tid], sMax[tid]);
}

// ---------------- tf32 tensor-core GEMM + fused attention logits ---------------
#define SMS 136
__device__ __forceinline__ uint32_t f2tf32(float v) {
    uint32_t r;
    asm("cvt.rna.tf32.f32 %0, %1;" : "=r"(r) : "f"(v));
    return r;
}
__device__ __forceinline__ void mma_tf32(float* c, uint32_t a0, uint32_t a1,
                                         uint32_t a2, uint32_t a3,
                                         uint32_t b0, uint32_t b1) {
    asm volatile(
        "mma.sync.aligned.m16n8k8.row.col.f32.tf32.tf32.f32 "
        "{%0,%1,%2,%3}, {%4,%5,%6,%7}, {%8,%9}, {%0,%1,%2,%3};"
        : "+f"(c[0]), "+f"(c[1]), "+f"(c[2]), "+f"(c[3])
        : "r"(a0), "r"(a1), "r"(a2), "r"(a3), "r"(b0), "r"(b1));
}

__global__ void __launch_bounds__(256, 2)
k_gemm_attn(const float* __restrict__ X, const float* __restrict__ W,
            const float* __restrict__ attS, const float* __restrict__ attD,
            float* __restrict__ C, float* __restrict__ aS, float* __restrict__ aD,
            float* __restrict__ maxS) {
    cudaGridDependencySynchronize();
    __shared__ uint32_t As[32][SMS];
    __shared__ uint32_t Bs[32][SMS];
    __shared__ float sS[128], sD[128];
    __shared__ float sPS[128][2], sPD[128][2];
    __shared__ float sMax[2];

    int tid = threadIdx.x;
    int lane = tid & 31;
    int w = tid >> 5;
    int wm = w & 1, wn = w >> 1;
    int r0 = blockIdx.x * 128;
    int c0 = blockIdx.y * 128;

    if (tid < 128) { sS[tid] = attS[c0 + tid]; sD[tid] = attD[c0 + tid]; }
    if (tid < 2) sMax[tid] = __int_as_float(0xff800000);
    {
        int rr = tid >> 1, hh = tid & 1;
        sPS[rr][hh] = 0.0f;
        sPD[rr][hh] = 0.0f;
    }

    float acc[4][4][4];
    #pragma unroll
    for (int i = 0; i < 4; i++)
        #pragma unroll
        for (int j = 0; j < 4; j++)
            #pragma unroll
            for (int q = 0; q < 4; q++) acc[i][j][q] = 0.0f;

    int am = tid >> 1;
    int ak = (tid & 1) * 16;
    int bkr = tid >> 3;
    int bn = (tid & 7) * 16;

    #pragma unroll 1
    for (int kc = 0; kc < DMODEL; kc += 32) {
        const float4* ap = (const float4*)(X + (r0 + am) * DMODEL + kc + ak);
        #pragma unroll
        for (int q = 0; q < 4; q++) {
            float4 v = ap[q];
            As[ak + q * 4 + 0][am] = f2tf32(v.x);
            As[ak + q * 4 + 1][am] = f2tf32(v.y);
            As[ak + q * 4 + 2][am] = f2tf32(v.z);
            As[ak + q * 4 + 3][am] = f2tf32(v.w);
        }
        const float4* bp = (const float4*)(W + (kc + bkr) * DMODEL + c0 + bn);
        #pragma unroll
        for (int q = 0; q < 4; q++) {
            float4 v = bp[q];
            uint4 u;
            u.x = f2tf32(v.x); u.y = f2tf32(v.y);
            u.z = f2tf32(v.z); u.w = f2tf32(v.w);
            *(uint4*)&Bs[bkr][bn + q * 4] = u;
        }
        __syncthreads();

        #pragma unroll
        for (int kk = 0; kk < 4; kk++) {
            int kb = kk * 8;
            int klo = kb + (lane & 3), khi = klo + 4;
            uint32_t afr[4][4], bfr[4][2];
            #pragma unroll
            for (int mt = 0; mt < 4; mt++) {
                int m = wm * 64 + mt * 16 + (lane >> 2);
                afr[mt][0] = As[klo][m];
                afr[mt][1] = As[klo][m + 8];
                afr[mt][2] = As[khi][m];
                afr[mt][3] = As[khi][m + 8];
            }
            #pragma unroll
            for (int nt = 0; nt < 4; nt++) {
                int n = wn * 32 + nt * 8 + (lane >> 2);
                bfr[nt][0] = Bs[klo][n];
                bfr[nt][1] = Bs[khi][n];
            }
            #pragma unroll
            for (int mt = 0; mt < 4; mt++)
                #pragma unroll
                for (int nt = 0; nt < 4; nt++)
                    mma_tf32(acc[mt][nt], afr[mt][0], afr[mt][1], afr[mt][2],
                             afr[mt][3], bfr[nt][0], bfr[nt][1]);
        }
        __syncthreads();
    }

    int hb = wn >> 1;
    #pragma unroll
    for (int mt = 0; mt < 4; mt++) {
        int rowA = wm * 64 + mt * 16 + (lane >> 2);
        int rowB = rowA + 8;
        float pSa = 0.0f, pDa = 0.0f, pSb = 0.0f, pDb = 0.0f;
        #pragma unroll
        for (int nt = 0; nt < 4; nt++) {
            int lc = wn * 32 + nt * 8 + 2 * (lane & 3);
            float s0 = sS[lc], s1 = sS[lc + 1];
            float d0 = sD[lc], d1 = sD[lc + 1];
            float* a = acc[mt][nt];
            pSa += a[0] * s0 + a[1] * s1;
            pDa += a[0] * d0 + a[1] * d1;
            pSb += a[2] * s0 + a[3] * s1;
            pDb += a[2] * d0 + a[3] * d1;
            float* cpA = C + (r0 + rowA) * DMODEL + c0 + lc;
            float* cpB = C + (r0 + rowB) * DMODEL + c0 + lc;
            *(float2*)cpA = make_float2(a[0], a[1]);
            *(float2*)cpB = make_float2(a[2], a[3]);
        }
        pSa += __shfl_xor_sync(0xffffffffu, pSa, 1);
        pSa += __shfl_xor_sync(0xffffffffu, pSa, 2);
        pDa += __shfl_xor_sync(0xffffffffu, pDa, 1);
        pDa += __shfl_xor_sync(0xffffffffu, pDa, 2);
        pSb += __shfl_xor_sync(0xffffffffu, pSb, 1);
        pSb += __shfl_xor_sync(0xffffffffu, pSb, 2);
        pDb += __shfl_xor_sync(0xffffffffu, pDb, 1);
        pDb += __shfl_xor_sync(0xffffffffu, pDb, 2);
        if ((lane & 3) == 0) {
            atomicAdd(&sPS[rowA][hb], pSa);
            atomicAdd(&sPD[rowA][hb], pDa);
            atomicAdd(&sPS[rowB][hb], pSb);
            atomicAdd(&sPD[rowB][hb], pDb);
        }
    }
    __syncthreads();
    {
        int rr = tid >> 1, hh = tid & 1;
        int node = r0 + rr;
        int head = blockIdx.y * 2 + hh;
        float v = sPS[rr][hh];
        aS[node * 4 + head] = v;
        aD[node * 4 + head] = sPD[rr][hh];
        atomicMaxF(&sMax[hh], v);
    }
    __syncthreads();
    if (tid < 2) atomicMaxF(&maxS[blockIdx.y * 2 + tid], sMax[tid]);
}

// ---------------- segment softmax + weighted aggregate --------------------------
__device__ __forceinline__ float lrelu(float v) { return v > 0.0f ? v : 0.2f * v; }

__device__ __forceinline__ void aggregate_node(
    int node, int lane, const int* __restrict__ rowptr, const int* __restrict__ csrc,
    const float* __restrict__ H, const float* __restrict__ aS,
    const float* __restrict__ aD, const float* __restrict__ bias,
    const float* __restrict__ maxS, float* __restrict__ ex, float r[8]) {
    int rs = rowptr[node], re = rowptr[node + 1];
    float4 ad = *(const float4*)(aD + node * 4);
    float4 mx = *(const float4*)maxS;
    float b0v = lrelu(mx.x + ad.x);
    float b1v = lrelu(mx.y + ad.y);
    float b2v = lrelu(mx.z + ad.z);
    float b3v = lrelu(mx.w + ad.w);

    float s0 = 0, s1 = 0, s2 = 0, s3 = 0;
    for (int e = rs + lane; e < re; e += 32) {
        int s = csrc[e];
        float4 as = *(const float4*)(aS + s * 4);
        float x0 = expf(lrelu(as.x + ad.x) - b0v);
        float x1 = expf(lrelu(as.y + ad.y) - b1v);
        float x2 = expf(lrelu(as.z + ad.z) - b2v);
        float x3 = expf(lrelu(as.w + ad.w) - b3v);
        *(float4*)(ex + e * 4) = make_float4(x0, x1, x2, x3);
        s0 += x0; s1 += x1; s2 += x2; s3 += x3;
    }
    #pragma unroll
    for (int o = 16; o > 0; o >>= 1) {
        s0 += __shfl_xor_sync(0xffffffffu, s0, o);
        s1 += __shfl_xor_sync(0xffffffffu, s1, o);
        s2 += __shfl_xor_sync(0xffffffffu, s2, o);
        s3 += __shfl_xor_sync(0xffffffffu, s3, o);
    }
    int head = lane >> 3;
    float sh = head == 0 ? s0 : head == 1 ? s1 : head == 2 ? s2 : s3;
    float inv = 1.0f / (sh + 1e-16f);

    float acc[8] = {};
    int cb = lane * 8;
    int sNext = csrc[rs];
    for (int e = rs; e < re; e++) {
        int s = sNext;
        if (e + 1 < re) sNext = csrc[e + 1];
        float xv = __ldg(ex + e * 4 + head);
        const float4* hp = (const float4*)(H + s * DMODEL + cb);
        float4 h0 = hp[0], h1 = hp[1];
        acc[0] += xv * h0.x; acc[1] += xv * h0.y;
        acc[2] += xv * h0.z; acc[3] += xv * h0.w;
        acc[4] += xv * h1.x; acc[5] += xv * h1.y;
        acc[6] += xv * h1.z; acc[7] += xv * h1.w;
    }
    const float4* bp = (const float4*)(bias + cb);
    float4 b0 = bp[0], b1 = bp[1];
    r[0] = acc[0] * inv + b0.x; r[1] = acc[1] * inv + b0.y;
    r[2] = acc[2] * inv + b0.z; r[3] = acc[3] * inv + b0.w;
    r[4] = acc[4] * inv + b1.x; r[5] = acc[5] * inv + b1.y;
    r[6] = acc[6] * inv + b1.z; r[7] = acc[7] * inv + b1.w;
    #pragma unroll
    for (int i = 0; i < 8; i++) r[i] = r[i] > 0.0f ? r[i] : 0.0f;
}

__global__ void k_aggregate(const int* __restrict__ rowptr, const int* __restrict__ csrc,
                            const float* __restrict__ H, const float* __restrict__ aS,
                            const float* __restrict__ aD, const float* __restrict__ bias,
                            const float* __restrict__ maxS,
                            float* __restrict__ ex, float* __restrict__ out) {
    cudaGridDependencySynchronize();
    int node = (blockIdx.x * blockDim.x + threadIdx.x) >> 5;
    int lane = threadIdx.x & 31;
    if (node >= NNODE) return;
    float r[8];
    aggregate_node(node, lane, rowptr, csrc, H, aS, aD, bias, maxS, ex, r);
    float* op = out + node * DMODEL + lane * 8;
    *(float4*)op       = make_float4(r[0], r[1], r[2], r[3]);
    *(float4*)(op + 4) = make_float4(r[4], r[5], r[6], r[7]);
}

// ---------------- epilogue: y = relu(X@Wg+bg); out = y@Wf+bf -------------------
// 64 nodes/block: Wg read once per 64 nodes (19 MB total vs 154 MB fused).
__global__ void __launch_bounds__(256)
k_final(const float* __restrict__ X, const float* __restrict__ Wg,
        const float* __restrict__ bg, const float* __restrict__ Wf,
        const float* __restrict__ bf, float* __restrict__ out) {
    cudaGridDependencySynchronize();
    __shared__ float sWg[64][FEAT];
    __shared__ float sy[FB][FEAT + 1];
    __shared__ float sWf[FEAT * 5];

    int tid = threadIdx.x;
    int node0 = blockIdx.x * FB;
    int nodeL = tid >> 2;
    int f0 = (tid & 3) * 16;

    for (int i = tid; i < FEAT * 5; i += 256) sWf[i] = Wf[i];

    float acc[16];
    {
        float4 g0 = *(const float4*)(bg + f0);
        float4 g1 = *(const float4*)(bg + f0 + 4);
        float4 g2 = *(const float4*)(bg + f0 + 8);
        float4 g3 = *(const float4*)(bg + f0 + 12);
        acc[0] = g0.x; acc[1] = g0.y; acc[2] = g0.z; acc[3] = g0.w;
        acc[4] = g1.x; acc[5] = g1.y; acc[6] = g1.z; acc[7] = g1.w;
        acc[8] = g2.x; acc[9] = g2.y; acc[10] = g2.z; acc[11] = g2.w;
        acc[12] = g3.x; acc[13] = g3.y; acc[14] = g3.z; acc[15] = g3.w;
    }

    const float* xr = X + (node0 + nodeL) * DMODEL;
    #pragma unroll 1
    for (int kc = 0; kc < DMODEL; kc += 64) {
        #pragma unroll
        for (int t2 = 0; t2 < 4; t2++) {
            int idx = (tid + t2 * 256) * 4;
            *(float4*)&sWg[idx >> 6][idx & 63] = *(const float4*)(Wg + (kc << 6) + idx);
        }
        __syncthreads();
        #pragma unroll
        for (int k4 = 0; k4 < 16; k4++) {
            float4 xv = *(const float4*)(xr + kc + k4 * 4);
            #pragma unroll
            for (int kk = 0; kk < 4; kk++) {
                float x = kk == 0 ? xv.x : kk == 1 ? xv.y : kk == 2 ? xv.z : xv.w;
                const float* wrow = &sWg[k4 * 4 + kk][f0];
                float4 w0 = *(const float4*)(wrow);
                float4 w1 = *(const float4*)(wrow + 4);
                float4 w2 = *(const float4*)(wrow + 8);
                float4 w3 = *(const float4*)(wrow + 12);
                acc[0] += x * w0.x; acc[1] += x * w0.y; acc[2] += x * w0.z; acc[3] += x * w0.w;
                acc[4] += x * w1.x; acc[5] += x * w1.y; acc[6] += x * w1.z; acc[7] += x * w1.w;
                acc[8] += x * w2.x; acc[9] += x * w2.y; acc[10] += x * w2.z; acc[11] += x * w2.w;
                acc[12] += x * w3.x; acc[13] += x * w3.y; acc[14] += x * w3.z; acc[15] += x * w3.w;
            }
        }
        __syncthreads();
    }
    #pragma unroll
    for (int j = 0; j < 16; j++) {
        float v = acc[j];
        sy[nodeL][f0 + j] = v > 0.0f ? v : 0.0f;
    }
    __syncthreads();

    for (int idx = tid; idx < FB * 5; idx += 256) {
        int n = idx / 5, c = idx % 5;
        float o = bf[c];
        #pragma unroll
        for (int k = 0; k < FEAT; k++) o += sy[n][k] * sWf[k * 5 + c];
        out[(node0 + n) * 5 + c] = o;
    }
}

// ---------------- host: PDL launch helper --------------------------------------
static inline void launch_pdl(const void* func, dim3 grid, dim3 block, void** args) {
    cudaLaunchConfig_t cfg = {};
    cfg.gridDim = grid;
    cfg.blockDim = block;
    cfg.dynamicSmemBytes = 0;
    cfg.stream = 0;
    cudaLaunchAttribute attr[1];
    attr[0].id = cudaLaunchAttributeProgrammaticStreamSerialization;
    attr[0].val.programmaticStreamSerializationAllowed = 1;
    cfg.attrs = attr;
    cfg.numAttrs = 1;
    cudaLaunchKernelExC(&cfg, func, args);
}

// ---------------- host orchestration ------------------------------------------
extern "C" void kernel_launch(void* const* d_in, const int* in_sizes, int n_in,
                              void* d_out, int out_size) {
    const float* z     = (const float*)d_in[0];
    const int*   ei    = (const int*)d_in[1];
    const int*   batch = (const int*)d_in[2];
    int base = (in_sizes[3] == 1) ? 4 : 3;
    const float* W0  = (const float*)d_in[base + 0];
    const float* b0  = (const float*)d_in[base + 1];
    const float* W1  = (const float*)d_in[base + 2];
    const float* as1 = (const float*)d_in[base + 3];
    const float* ad1 = (const float*)d_in[base + 4];
    const float* bb1 = (const float*)d_in[base + 5];
    const float* W2  = (const float*)d_in[base + 6];
    const float* as2 = (const float*)d_in[base + 7];
    const float* ad2 = (const float*)d_in[base + 8];
    const float* bb2 = (const float*)d_in[base + 9];
    const float* W3  = (const float*)d_in[base + 10];
    const float* as3 = (const float*)d_in[base + 11];
    const float* ad3 = (const float*)d_in[base + 12];
    const float* bb3 = (const float*)d_in[base + 13];
    const float* Wg  = (const float*)d_in[base + 14];
    const float* bg  = (const float*)d_in[base + 15];
    const float* Wf  = (const float*)d_in[base + 16];
    const float* bf  = (const float*)d_in[base + 17];

    const int* srcArr = ei;
    const int* dstArr = ei + NEDGE;

    float *bufA, *bufB, *aS, *aD, *exB, *pgB, *maxB;
    int *startsB, *degB, *rowptrB, *cursorB, *csrcB;
    cudaGetSymbolAddress((void**)&bufA, g_bufA);
    cudaGetSymbolAddress((void**)&bufB, g_bufB);
    cudaGetSymbolAddress((void**)&aS, g_as);
    cudaGetSymbolAddress((void**)&aD, g_ad);
    cudaGetSymbolAddress((void**)&exB, g_ex);
    cudaGetSymbolAddress((void**)&pgB, g_pg);
    cudaGetSymbolAddress((void**)&maxB, g_maxS);
    cudaGetSymbolAddress((void**)&startsB, g_starts);
    cudaGetSymbolAddress((void**)&degB, g_deg);
    cudaGetSymbolAddress((void**)&rowptrB, g_rowptr);
    cudaGetSymbolAddress((void**)&cursorB, g_cursor);
    cudaGetSymbolAddress((void**)&csrcB, g_csrc);

    float* max0 = maxB;
    float* max1 = maxB + 4;
    float* max2 = maxB + 8;
    float* outP = (float*)d_out;

    {   // 1: prologue
        void* a[] = {&z, &W0, &b0, &W1, &pgB, &batch, &startsB, &degB, &dstArr};
        launch_pdl((const void*)k_pro, dim3(NGRAPH + NBLK + EBLK), dim3(256), a);
    }
    {   // 2: CSR rowptr + fill
        void* a[] = {&degB, &rowptrB, &cursorB, &csrcB, &maxB};
        launch_pdl((const void*)k_fill2, dim3(NBLK), dim3(256), a);
    }
    {   // 3: h1+attn | scatter | deg re-zero
        void* a[] = {&pgB, &W1, &batch, &startsB, &as1, &ad1, &bufB, &aS, &aD,
                     &srcArr, &dstArr, &cursorB, &csrcB, &degB, &max0};
        launch_pdl((const void*)k_mid, dim3(WBLK + EBLK + NBLK), dim3(256), a);
    }
    {   // 4: aggregate layer 1
        void* a[] = {&rowptrB, &csrcB, &bufB, &aS, &aD, &bb1, &max0, &exB, &bufA};
        launch_pdl((const void*)k_aggregate, dim3(WBLK), dim3(256), a);
    }
    {   // 5: layer-2 GEMM
        void* a[] = {&bufA, &W2, &as2, &ad2, &bufB, &aS, &aD, &max1};
        launch_pdl((const void*)k_gemm_attn, dim3(NNODE / 128, 2), dim3(256), a);
    }
    {   // 6: aggregate layer 2
        void* a[] = {&rowptrB, &csrcB, &bufB, &aS, &aD, &bb2, &max1, &exB, &bufA};
        launch_pdl((const void*)k_aggregate, dim3(WBLK), dim3(256), a);
    }
    {   // 7: layer-3 GEMM
        void* a[] = {&bufA, &W3, &as3, &ad3, &bufB, &aS, &aD, &max2};
        launch_pdl((const void*)k_gemm_attn, dim3(NNODE / 128, 2), dim3(256), a);
    }
    {   // 8: aggregate layer 3 -> bufA
        void* a[] = {&rowptrB, &csrcB, &bufB, &aS, &aD, &bb3, &max2, &exB, &bufA};
        launch_pdl((const void*)k_aggregate, dim3(WBLK), dim3(256), a);
    }
    {   // 9: dec_geo + fc_geo epilogue
        void* a[] = {&bufA, &Wg, &bg, &Wf, &bf, &outP};
        launch_pdl((const void*)k_final, dim3(NNODE / FB), dim3(256), a);
    }
}

// round 15
// speedup vs baseline: 1.1803x; 1.1803x over previous
#include <cuda_runtime.h>
#include <math.h>
#include <stdint.h>

// ---------------- problem constants -----------------------------------------
#define NNODE 19200
#define NEDGE 230400
#define NGRAPH 128
#define LATENT 256
#define FEAT 64
#define HEADS 4
#define POS 180
#define DMODEL 256       // HEADS * FEAT
#define ETOT (NEDGE + NNODE)
#define NBLK 75          // NNODE / 256
#define EBLK 900         // NEDGE / 256
#define WBLK 2400        // NNODE / 8 (8 warps per block)
#define AFBLK 1200       // NNODE / 16 (k_agg_final: 2 nodes per warp)

// ---------------- static device scratch --------------------------------------
__device__ __align__(16) float g_bufA[NNODE * DMODEL];
__device__ __align__(16) float g_bufB[NNODE * DMODEL];
__device__ __align__(16) float g_as[NNODE * HEADS];
__device__ __align__(16) float g_ad[NNODE * HEADS];
__device__ __align__(16) float g_ex[ETOT * HEADS];
__device__ __align__(16) float g_pg[NGRAPH * DMODEL];
__device__ __align__(16) float g_maxS[3][4];   // per-layer global aS max (slots)
__device__ int g_starts[NGRAPH];
__device__ int g_deg[NNODE];      // zero at load; re-zeroed each replay in k_mid
__device__ int g_rowptr[NNODE + 1];
__device__ int g_cursor[NNODE];
__device__ int g_csrc[ETOT];

__device__ __forceinline__ void atomicMaxF(float* a, float v) {
    if (v >= 0.0f) atomicMax((int*)a, __float_as_int(v));
    else           atomicMin((unsigned int*)a, __float_as_uint(v));
}

// ---------------- fused prologue: x0pg | starts | hist -------------------------
__global__ void k_pro(const float* __restrict__ z, const float* __restrict__ W0,
                      const float* __restrict__ b0, const float* __restrict__ W1,
                      float* __restrict__ pg, const int* __restrict__ batch,
                      int* __restrict__ starts, int* __restrict__ deg,
                      const int* __restrict__ dst) {
    cudaGridDependencySynchronize();
    int b = blockIdx.x;
    int t = threadIdx.x;
    if (b < NGRAPH) {
        __shared__ float xs[FEAT];
        if (t < FEAT) {
            float acc = b0[t];
            const float* zr = z + b * LATENT;
            #pragma unroll 4
            for (int k = 0; k < LATENT; k++) acc += zr[k] * W0[k * FEAT + t];
            xs[t] = acc > 0.0f ? acc : 0.0f;
        }
        __syncthreads();
        float a = 0.0f;
        #pragma unroll
        for (int k = 0; k < FEAT; k++) a += xs[k] * W1[k * DMODEL + t];
        pg[b * DMODEL + t] = a;
    } else if (b < NGRAPH + NBLK) {
        int i = (b - NGRAPH) * 256 + t;
        int bb = batch[i];
        if (i == 0 || batch[i - 1] != bb) starts[bb] = i;
    } else {
        int e = (b - NGRAPH - NBLK) * 256 + t;
        atomicAdd(&deg[dst[e]], 1);
    }
}

// ---------------- CSR: prefix + local scan + self-loop fill + maxS init --------
__global__ void k_fill2(const int* __restrict__ deg, int* __restrict__ rowptr,
                        int* __restrict__ cursor, int* __restrict__ csrc,
                        float* __restrict__ maxS) {
    cudaGridDependencySynchronize();
    __shared__ int red[256];
    __shared__ int s[256];
    int t = threadIdx.x;
    int b = blockIdx.x;
    if (b == 0 && t < 12) maxS[t] = __int_as_float(0xff800000);  // -inf, 3 slots
    int lim = b * 256;
    int sum = 0;
    for (int i = t; i < lim; i += 256) sum += deg[i] + 1;   // +1 self loop
    red[t] = sum;
    __syncthreads();
    for (int off = 128; off > 0; off >>= 1) {
        if (t < off) red[t] += red[t + off];
        __syncthreads();
    }
    int node = lim + t;
    int d = deg[node] + 1;
    s[t] = d;
    __syncthreads();
    for (int off = 1; off < 256; off <<= 1) {
        int u = (t >= off) ? s[t - off] : 0;
        __syncthreads();
        s[t] += u;
        __syncthreads();
    }
    int r = red[0] + s[t] - d;
    rowptr[node] = r;
    csrc[r] = node;                           // self loop first
    cursor[node] = r + 1;
    if (node == NNODE - 1) rowptr[NNODE] = red[0] + s[t];
}

// ---------------- fused: h1+attn | CSR scatter | deg re-zero --------------------
__global__ void k_mid(const float* __restrict__ pg, const float* __restrict__ W1,
                      const int* __restrict__ batch, const int* __restrict__ starts,
                      const float* __restrict__ attS, const float* __restrict__ attD,
                      float* __restrict__ H, float* __restrict__ aS,
                      float* __restrict__ aD,
                      const int* __restrict__ src, const int* __restrict__ dst,
                      int* __restrict__ cursor, int* __restrict__ csrc,
                      int* __restrict__ deg, float* __restrict__ maxS) {
    cudaGridDependencySynchronize();
    int b = blockIdx.x;
    int tid = threadIdx.x;
    if (b >= WBLK + EBLK) {
        deg[(b - WBLK - EBLK) * 256 + tid] = 0;
        return;
    }
    if (b >= WBLK) {
        int e = (b - WBLK) * 256 + tid;
        int p = atomicAdd(&cursor[dst[e]], 1);
        csrc[p] = src[e];
        return;
    }
    __shared__ float sS[DMODEL], sD[DMODEL];
    __shared__ float sMax[4];
    if (tid < DMODEL) { sS[tid] = attS[tid]; sD[tid] = attD[tid]; }
    if (tid < 4) sMax[tid] = __int_as_float(0xff800000);
    __syncthreads();
    int node = b * 8 + (tid >> 5);
    int lane = tid & 31;
    int g = batch[node];
    int order = node - starts[g];
    int c0 = lane * 8;
    const float4* pgr = (const float4*)(pg + g * DMODEL + c0);
    const float4* w1r = (const float4*)(W1 + (FEAT + order) * DMODEL + c0);
    float4 p0 = pgr[0], p1 = pgr[1];
    float4 w0 = w1r[0], w1v = w1r[1];
    float h[8];
    h[0] = p0.x + w0.x; h[1] = p0.y + w0.y; h[2] = p0.z + w0.z; h[3] = p0.w + w0.w;
    h[4] = p1.x + w1v.x; h[5] = p1.y + w1v.y; h[6] = p1.z + w1v.z; h[7] = p1.w + w1v.w;
    float* hr = H + node * DMODEL + c0;
    *(float4*)hr       = make_float4(h[0], h[1], h[2], h[3]);
    *(float4*)(hr + 4) = make_float4(h[4], h[5], h[6], h[7]);
    float pS = 0.0f, pD = 0.0f;
    #pragma unroll
    for (int j = 0; j < 8; j++) { pS += h[j] * sS[c0 + j]; pD += h[j] * sD[c0 + j]; }
    pS += __shfl_xor_sync(0xffffffffu, pS, 1);
    pS += __shfl_xor_sync(0xffffffffu, pS, 2);
    pS += __shfl_xor_sync(0xffffffffu, pS, 4);
    pD += __shfl_xor_sync(0xffffffffu, pD, 1);
    pD += __shfl_xor_sync(0xffffffffu, pD, 2);
    pD += __shfl_xor_sync(0xffffffffu, pD, 4);
    if ((lane & 7) == 0) {
        int hd = lane >> 3;
        aS[node * 4 + hd] = pS;
        aD[node * 4 + hd] = pD;
        atomicMaxF(&sMax[hd], pS);
    }
    __syncthreads();
    if (tid < 4) atomicMaxF(&maxS[tid], sMax[tid]);
}

// ---------------- tf32 tensor-core GEMM + fused attention logits ---------------
#define SMS 136
__device__ __forceinline__ uint32_t f2tf32(float v) {
    uint32_t r;
    asm("cvt.rna.tf32.f32 %0, %1;" : "=r"(r) : "f"(v));
    return r;
}
__device__ __forceinline__ void mma_tf32(float* c, uint32_t a0, uint32_t a1,
                                         uint32_t a2, uint32_t a3,
                                         uint32_t b0, uint32_t b1) {
    asm volatile(
        "mma.sync.aligned.m16n8k8.row.col.f32.tf32.tf32.f32 "
        "{%0,%1,%2,%3}, {%4,%5,%6,%7}, {%8,%9}, {%0,%1,%2,%3};"
        : "+f"(c[0]), "+f"(c[1]), "+f"(c[2]), "+f"(c[3])
        : "r"(a0), "r"(a1), "r"(a2), "r"(a3), "r"(b0), "r"(b1));
}

__global__ void __launch_bounds__(256, 2)
k_gemm_attn(const float* __restrict__ X, const float* __restrict__ W,
            const float* __restrict__ attS, const float* __restrict__ attD,
            float* __restrict__ C, float* __restrict__ aS, float* __restrict__ aD,
            float* __restrict__ maxS) {
    cudaGridDependencySynchronize();
    __shared__ uint32_t As[32][SMS];
    __shared__ uint32_t Bs[32][SMS];
    __shared__ float sS[128], sD[128];
    __shared__ float sPS[128][2], sPD[128][2];
    __shared__ float sMax[2];

    int tid = threadIdx.x;
    int lane = tid & 31;
    int w = tid >> 5;
    int wm = w & 1, wn = w >> 1;
    int r0 = blockIdx.x * 128;
    int c0 = blockIdx.y * 128;

    if (tid < 128) { sS[tid] = attS[c0 + tid]; sD[tid] = attD[c0 + tid]; }
    if (tid < 2) sMax[tid] = __int_as_float(0xff800000);
    {
        int rr = tid >> 1, hh = tid & 1;
        sPS[rr][hh] = 0.0f;
        sPD[rr][hh] = 0.0f;
    }

    float acc[4][4][4];
    #pragma unroll
    for (int i = 0; i < 4; i++)
        #pragma unroll
        for (int j = 0; j < 4; j++)
            #pragma unroll
            for (int q = 0; q < 4; q++) acc[i][j][q] = 0.0f;

    int am = tid >> 1;
    int ak = (tid & 1) * 16;
    int bkr = tid >> 3;
    int bn = (tid & 7) * 16;

    #pragma unroll 1
    for (int kc = 0; kc < DMODEL; kc += 32) {
        const float4* ap = (const float4*)(X + (r0 + am) * DMODEL + kc + ak);
        #pragma unroll
        for (int q = 0; q < 4; q++) {
            float4 v = ap[q];
            As[ak + q * 4 + 0][am] = f2tf32(v.x);
            As[ak + q * 4 + 1][am] = f2tf32(v.y);
            As[ak + q * 4 + 2][am] = f2tf32(v.z);
            As[ak + q * 4 + 3][am] = f2tf32(v.w);
        }
        const float4* bp = (const float4*)(W + (kc + bkr) * DMODEL + c0 + bn);
        #pragma unroll
        for (int q = 0; q < 4; q++) {
            float4 v = bp[q];
            uint4 u;
            u.x = f2tf32(v.x); u.y = f2tf32(v.y);
            u.z = f2tf32(v.z); u.w = f2tf32(v.w);
            *(uint4*)&Bs[bkr][bn + q * 4] = u;
        }
        __syncthreads();

        #pragma unroll
        for (int kk = 0; kk < 4; kk++) {
            int kb = kk * 8;
            int klo = kb + (lane & 3), khi = klo + 4;
            uint32_t afr[4][4], bfr[4][2];
            #pragma unroll
            for (int mt = 0; mt < 4; mt++) {
                int m = wm * 64 + mt * 16 + (lane >> 2);
                afr[mt][0] = As[klo][m];
                afr[mt][1] = As[klo][m + 8];
                afr[mt][2] = As[khi][m];
                afr[mt][3] = As[khi][m + 8];
            }
            #pragma unroll
            for (int nt = 0; nt < 4; nt++) {
                int n = wn * 32 + nt * 8 + (lane >> 2);
                bfr[nt][0] = Bs[klo][n];
                bfr[nt][1] = Bs[khi][n];
            }
            #pragma unroll
            for (int mt = 0; mt < 4; mt++)
                #pragma unroll
                for (int nt = 0; nt < 4; nt++)
                    mma_tf32(acc[mt][nt], afr[mt][0], afr[mt][1], afr[mt][2],
                             afr[mt][3], bfr[nt][0], bfr[nt][1]);
        }
        __syncthreads();
    }

    int hb = wn >> 1;
    #pragma unroll
    for (int mt = 0; mt < 4; mt++) {
        int rowA = wm * 64 + mt * 16 + (lane >> 2);
        int rowB = rowA + 8;
        float pSa = 0.0f, pDa = 0.0f, pSb = 0.0f, pDb = 0.0f;
        #pragma unroll
        for (int nt = 0; nt < 4; nt++) {
            int lc = wn * 32 + nt * 8 + 2 * (lane & 3);
            float s0 = sS[lc], s1 = sS[lc + 1];
            float d0 = sD[lc], d1 = sD[lc + 1];
            float* a = acc[mt][nt];
            pSa += a[0] * s0 + a[1] * s1;
            pDa += a[0] * d0 + a[1] * d1;
            pSb += a[2] * s0 + a[3] * s1;
            pDb += a[2] * d0 + a[3] * d1;
            float* cpA = C + (r0 + rowA) * DMODEL + c0 + lc;
            float* cpB = C + (r0 + rowB) * DMODEL + c0 + lc;
            *(float2*)cpA = make_float2(a[0], a[1]);
            *(float2*)cpB = make_float2(a[2], a[3]);
        }
        pSa += __shfl_xor_sync(0xffffffffu, pSa, 1);
        pSa += __shfl_xor_sync(0xffffffffu, pSa, 2);
        pDa += __shfl_xor_sync(0xffffffffu, pDa, 1);
        pDa += __shfl_xor_sync(0xffffffffu, pDa, 2);
        pSb += __shfl_xor_sync(0xffffffffu, pSb, 1);
        pSb += __shfl_xor_sync(0xffffffffu, pSb, 2);
        pDb += __shfl_xor_sync(0xffffffffu, pDb, 1);
        pDb += __shfl_xor_sync(0xffffffffu, pDb, 2);
        if ((lane & 3) == 0) {
            atomicAdd(&sPS[rowA][hb], pSa);
            atomicAdd(&sPD[rowA][hb], pDa);
            atomicAdd(&sPS[rowB][hb], pSb);
            atomicAdd(&sPD[rowB][hb], pDb);
        }
    }
    __syncthreads();
    {
        int rr = tid >> 1, hh = tid & 1;
        int node = r0 + rr;
        int head = blockIdx.y * 2 + hh;
        float v = sPS[rr][hh];
        aS[node * 4 + head] = v;
        aD[node * 4 + head] = sPD[rr][hh];
        atomicMaxF(&sMax[hh], v);
    }
    __syncthreads();
    if (tid < 2) atomicMaxF(&maxS[blockIdx.y * 2 + tid], sMax[tid]);
}

// ---------------- segment softmax + weighted aggregate --------------------------
__device__ __forceinline__ float lrelu(float v) { return v > 0.0f ? v : 0.2f * v; }

__device__ __forceinline__ void aggregate_node(
    int node, int lane, const int* __restrict__ rowptr, const int* __restrict__ csrc,
    const float* __restrict__ H, const float* __restrict__ aS,
    const float* __restrict__ aD, const float* __restrict__ bias,
    const float* __restrict__ maxS, float* __restrict__ ex, float r[8]) {
    int rs = rowptr[node], re = rowptr[node + 1];
    float4 ad = *(const float4*)(aD + node * 4);
    float4 mx = *(const float4*)maxS;
    float b0v = lrelu(mx.x + ad.x);
    float b1v = lrelu(mx.y + ad.y);
    float b2v = lrelu(mx.z + ad.z);
    float b3v = lrelu(mx.w + ad.w);

    float s0 = 0, s1 = 0, s2 = 0, s3 = 0;
    for (int e = rs + lane; e < re; e += 32) {
        int s = csrc[e];
        float4 as = *(const float4*)(aS + s * 4);
        float x0 = expf(lrelu(as.x + ad.x) - b0v);
        float x1 = expf(lrelu(as.y + ad.y) - b1v);
        float x2 = expf(lrelu(as.z + ad.z) - b2v);
        float x3 = expf(lrelu(as.w + ad.w) - b3v);
        *(float4*)(ex + e * 4) = make_float4(x0, x1, x2, x3);
        s0 += x0; s1 += x1; s2 += x2; s3 += x3;
    }
    #pragma unroll
    for (int o = 16; o > 0; o >>= 1) {
        s0 += __shfl_xor_sync(0xffffffffu, s0, o);
        s1 += __shfl_xor_sync(0xffffffffu, s1, o);
        s2 += __shfl_xor_sync(0xffffffffu, s2, o);
        s3 += __shfl_xor_sync(0xffffffffu, s3, o);
    }
    int head = lane >> 3;
    float sh = head == 0 ? s0 : head == 1 ? s1 : head == 2 ? s2 : s3;
    float inv = 1.0f / (sh + 1e-16f);

    float acc[8] = {};
    int cb = lane * 8;
    int sNext = csrc[rs];
    for (int e = rs; e < re; e++) {
        int s = sNext;
        if (e + 1 < re) sNext = csrc[e + 1];
        float xv = __ldg(ex + e * 4 + head);
        const float4* hp = (const float4*)(H + s * DMODEL + cb);
        float4 h0 = hp[0], h1 = hp[1];
        acc[0] += xv * h0.x; acc[1] += xv * h0.y;
        acc[2] += xv * h0.z; acc[3] += xv * h0.w;
        acc[4] += xv * h1.x; acc[5] += xv * h1.y;
        acc[6] += xv * h1.z; acc[7] += xv * h1.w;
    }
    const float4* bp = (const float4*)(bias + cb);
    float4 b0 = bp[0], b1 = bp[1];
    r[0] = acc[0] * inv + b0.x; r[1] = acc[1] * inv + b0.y;
    r[2] = acc[2] * inv + b0.z; r[3] = acc[3] * inv + b0.w;
    r[4] = acc[4] * inv + b1.x; r[5] = acc[5] * inv + b1.y;
    r[6] = acc[6] * inv + b1.z; r[7] = acc[7] * inv + b1.w;
    #pragma unroll
    for (int i = 0; i < 8; i++) r[i] = r[i] > 0.0f ? r[i] : 0.0f;
}

__global__ void k_aggregate(const int* __restrict__ rowptr, const int* __restrict__ csrc,
                            const float* __restrict__ H, const float* __restrict__ aS,
                            const float* __restrict__ aD, const float* __restrict__ bias,
                            const float* __restrict__ maxS,
                            float* __restrict__ ex, float* __restrict__ out) {
    cudaGridDependencySynchronize();
    int node = (blockIdx.x * blockDim.x + threadIdx.x) >> 5;
    int lane = threadIdx.x & 31;
    if (node >= NNODE) return;
    float r[8];
    aggregate_node(node, lane, rowptr, csrc, H, aS, aD, bias, maxS, ex, r);
    float* op = out + node * DMODEL + lane * 8;
    *(float4*)op       = make_float4(r[0], r[1], r[2], r[3]);
    *(float4*)(op + 4) = make_float4(r[4], r[5], r[6], r[7]);
}

// ---------------- fused: layer-3 aggregate + dec_geo + fc_geo ------------------
// 16 nodes per block (2 per warp) to halve the per-block Wg staging traffic.
__global__ void __launch_bounds__(256)
k_agg_final(const int* __restrict__ rowptr, const int* __restrict__ csrc,
            const float* __restrict__ H, const float* __restrict__ aS,
            const float* __restrict__ aD, const float* __restrict__ bias,
            const float* __restrict__ maxS, float* __restrict__ ex,
            const float* __restrict__ Wg, const float* __restrict__ bg,
            const float* __restrict__ Wf, const float* __restrict__ bf,
            float* __restrict__ out) {
    cudaGridDependencySynchronize();
    __shared__ float sWg[128][FEAT];          // 32 KB chunk of Wg
    __shared__ float sx[16][DMODEL];          // 16 KB node features
    __shared__ float sWf[FEAT * 5];

    int tid = threadIdx.x;
    int w = tid >> 5;
    int lane = tid & 31;
    int nodeA = blockIdx.x * 16 + w * 2;
    int nodeB = nodeA + 1;

    for (int i = tid; i < FEAT * 5; i += 256) sWf[i] = Wf[i];

    float r[8];
    aggregate_node(nodeA, lane, rowptr, csrc, H, aS, aD, bias, maxS, ex, r);
    {
        float* sxp = &sx[w * 2][lane * 8];
        *(float4*)sxp       = make_float4(r[0], r[1], r[2], r[3]);
        *(float4*)(sxp + 4) = make_float4(r[4], r[5], r[6], r[7]);
    }
    aggregate_node(nodeB, lane, rowptr, csrc, H, aS, aD, bias, maxS, ex, r);
    {
        float* sxp = &sx[w * 2 + 1][lane * 8];
        *(float4*)sxp       = make_float4(r[0], r[1], r[2], r[3]);
        *(float4*)(sxp + 4) = make_float4(r[4], r[5], r[6], r[7]);
    }
    __syncthreads();

    // y for both nodes; thread owns columns lane and lane+32
    float ya0 = bg[lane], ya1 = bg[lane + 32];
    float yb0 = ya0, yb1 = ya1;
    #pragma unroll 1
    for (int kc = 0; kc < DMODEL; kc += 128) {
        #pragma unroll
        for (int t2 = 0; t2 < 8; t2++) {
            int idx = (tid + t2 * 256) * 4;
            *(float4*)&sWg[idx >> 6][idx & 63] =
                *(const float4*)(Wg + kc * FEAT + idx);
        }
        __syncthreads();
        #pragma unroll 4
        for (int k = 0; k < 128; k++) {
            float wv0 = sWg[k][lane];
            float wv1 = sWg[k][lane + 32];
            float xa = sx[w * 2][kc + k];
            float xb = sx[w * 2 + 1][kc + k];
            ya0 += xa * wv0; ya1 += xa * wv1;
            yb0 += xb * wv0; yb1 += xb * wv1;
        }
        __syncthreads();
    }
    ya0 = ya0 > 0.0f ? ya0 : 0.0f;
    ya1 = ya1 > 0.0f ? ya1 : 0.0f;
    yb0 = yb0 > 0.0f ? yb0 : 0.0f;
    yb1 = yb1 > 0.0f ? yb1 : 0.0f;

    float pa[5], pb[5];
    #pragma unroll
    for (int c = 0; c < 5; c++) {
        float w0 = sWf[lane * 5 + c], w1 = sWf[(lane + 32) * 5 + c];
        pa[c] = ya0 * w0 + ya1 * w1;
        pb[c] = yb0 * w0 + yb1 * w1;
    }
    #pragma unroll
    for (int o = 16; o > 0; o >>= 1) {
        #pragma unroll
        for (int c = 0; c < 5; c++) {
            pa[c] += __shfl_xor_sync(0xffffffffu, pa[c], o);
            pb[c] += __shfl_xor_sync(0xffffffffu, pb[c], o);
        }
    }
    if (lane == 0) {
        #pragma unroll
        for (int c = 0; c < 5; c++) {
            out[nodeA * 5 + c] = pa[c] + bf[c];
            out[nodeB * 5 + c] = pb[c] + bf[c];
        }
    }
}

// ---------------- host: PDL launch helper --------------------------------------
static inline void launch_pdl(const void* func, dim3 grid, dim3 block, void** args) {
    cudaLaunchConfig_t cfg = {};
    cfg.gridDim = grid;
    cfg.blockDim = block;
    cfg.dynamicSmemBytes = 0;
    cfg.stream = 0;
    cudaLaunchAttribute attr[1];
    attr[0].id = cudaLaunchAttributeProgrammaticStreamSerialization;
    attr[0].val.programmaticStreamSerializationAllowed = 1;
    cfg.attrs = attr;
    cfg.numAttrs = 1;
    cudaLaunchKernelExC(&cfg, func, args);
}

// ---------------- host orchestration ------------------------------------------
extern "C" void kernel_launch(void* const* d_in, const int* in_sizes, int n_in,
                              void* d_out, int out_size) {
    const float* z     = (const float*)d_in[0];
    const int*   ei    = (const int*)d_in[1];
    const int*   batch = (const int*)d_in[2];
    int base = (in_sizes[3] == 1) ? 4 : 3;
    const float* W0  = (const float*)d_in[base + 0];
    const float* b0  = (const float*)d_in[base + 1];
    const float* W1  = (const float*)d_in[base + 2];
    const float* as1 = (const float*)d_in[base + 3];
    const float* ad1 = (const float*)d_in[base + 4];
    const float* bb1 = (const float*)d_in[base + 5];
    const float* W2  = (const float*)d_in[base + 6];
    const float* as2 = (const float*)d_in[base + 7];
    const float* ad2 = (const float*)d_in[base + 8];
    const float* bb2 = (const float*)d_in[base + 9];
    const float* W3  = (const float*)d_in[base + 10];
    const float* as3 = (const float*)d_in[base + 11];
    const float* ad3 = (const float*)d_in[base + 12];
    const float* bb3 = (const float*)d_in[base + 13];
    const float* Wg  = (const float*)d_in[base + 14];
    const float* bg  = (const float*)d_in[base + 15];
    const float* Wf  = (const float*)d_in[base + 16];
    const float* bf  = (const float*)d_in[base + 17];

    const int* srcArr = ei;
    const int* dstArr = ei + NEDGE;

    float *bufA, *bufB, *aS, *aD, *exB, *pgB, *maxB;
    int *startsB, *degB, *rowptrB, *cursorB, *csrcB;
    cudaGetSymbolAddress((void**)&bufA, g_bufA);
    cudaGetSymbolAddress((void**)&bufB, g_bufB);
    cudaGetSymbolAddress((void**)&aS, g_as);
    cudaGetSymbolAddress((void**)&aD, g_ad);
    cudaGetSymbolAddress((void**)&exB, g_ex);
    cudaGetSymbolAddress((void**)&pgB, g_pg);
    cudaGetSymbolAddress((void**)&maxB, g_maxS);
    cudaGetSymbolAddress((void**)&startsB, g_starts);
    cudaGetSymbolAddress((void**)&degB, g_deg);
    cudaGetSymbolAddress((void**)&rowptrB, g_rowptr);
    cudaGetSymbolAddress((void**)&cursorB, g_cursor);
    cudaGetSymbolAddress((void**)&csrcB, g_csrc);

    float* max0 = maxB;
    float* max1 = maxB + 4;
    float* max2 = maxB + 8;
    float* outP = (float*)d_out;

    {   // 1: prologue
        void* a[] = {&z, &W0, &b0, &W1, &pgB, &batch, &startsB, &degB, &dstArr};
        launch_pdl((const void*)k_pro, dim3(NGRAPH + NBLK + EBLK), dim3(256), a);
    }
    {   // 2: CSR rowptr + fill
        void* a[] = {&degB, &rowptrB, &cursorB, &csrcB, &maxB};
        launch_pdl((const void*)k_fill2, dim3(NBLK), dim3(256), a);
    }
    {   // 3: h1+attn | scatter | deg re-zero
        void* a[] = {&pgB, &W1, &batch, &startsB, &as1, &ad1, &bufB, &aS, &aD,
                     &srcArr, &dstArr, &cursorB, &csrcB, &degB, &max0};
        launch_pdl((const void*)k_mid, dim3(WBLK + EBLK + NBLK), dim3(256), a);
    }
    {   // 4: aggregate layer 1
        void* a[] = {&rowptrB, &csrcB, &bufB, &aS, &aD, &bb1, &max0, &exB, &bufA};
        launch_pdl((const void*)k_aggregate, dim3(WBLK), dim3(256), a);
    }
    {   // 5: layer-2 GEMM
        void* a[] = {&bufA, &W2, &as2, &ad2, &bufB, &aS, &aD, &max1};
        launch_pdl((const void*)k_gemm_attn, dim3(NNODE / 128, 2), dim3(256), a);
    }
    {   // 6: aggregate layer 2
        void* a[] = {&rowptrB, &csrcB, &bufB, &aS, &aD, &bb2, &max1, &exB, &bufA};
        launch_pdl((const void*)k_aggregate, dim3(WBLK), dim3(256), a);
    }
    {   // 7: layer-3 GEMM
        void* a[] = {&bufA, &W3, &as3, &ad3, &bufB, &aS, &aD, &max2};
        launch_pdl((const void*)k_gemm_attn, dim3(NNODE / 128, 2), dim3(256), a);
    }
    {   // 8: layer-3 aggregate fused with dec_geo + fc_geo (16 nodes/block)
        void* a[] = {&rowptrB, &csrcB, &bufB, &aS, &aD, &bb3, &max2, &exB,
                     &Wg, &bg, &Wf, &bf, &outP};
        launch_pdl((const void*)k_agg_final, dim3(AFBLK), dim3(256), a);
    }
}

// round 16
// speedup vs baseline: 1.2504x; 1.0594x over previous
#include <cuda_runtime.h>
#include <math.h>
#include <stdint.h>

// ---------------- problem constants -----------------------------------------
#define NNODE 19200
#define NEDGE 230400
#define NGRAPH 128
#define LATENT 256
#define FEAT 64
#define HEADS 4
#define POS 180
#define DMODEL 256       // HEADS * FEAT
#define ETOT (NEDGE + NNODE)
#define NBLK 75          // NNODE / 256
#define EBLK 900         // NEDGE / 256
#define WBLK 2400        // NNODE / 8 (8 warps per block)
#define AFBLK 600        // NNODE / 32 (k_agg_final: 4 nodes per warp)

// ---------------- static device scratch --------------------------------------
__device__ __align__(16) float g_bufA[NNODE * DMODEL];
__device__ __align__(16) float g_bufB[NNODE * DMODEL];
__device__ __align__(16) float g_as[NNODE * HEADS];
__device__ __align__(16) float g_ad[NNODE * HEADS];
__device__ __align__(16) float g_ex[ETOT * HEADS];
__device__ __align__(16) float g_pg[NGRAPH * DMODEL];
__device__ __align__(16) float g_maxS[3][4];   // per-layer global aS max (slots)
__device__ int g_starts[NGRAPH];
__device__ int g_deg[NNODE];      // zero at load; re-zeroed each replay in k_mid
__device__ int g_rowptr[NNODE + 1];
__device__ int g_cursor[NNODE];
__device__ int g_csrc[ETOT];

__device__ __forceinline__ void atomicMaxF(float* a, float v) {
    if (v >= 0.0f) atomicMax((int*)a, __float_as_int(v));
    else           atomicMin((unsigned int*)a, __float_as_uint(v));
}

// ---------------- fused prologue: x0pg | starts | hist -------------------------
__global__ void k_pro(const float* __restrict__ z, const float* __restrict__ W0,
                      const float* __restrict__ b0, const float* __restrict__ W1,
                      float* __restrict__ pg, const int* __restrict__ batch,
                      int* __restrict__ starts, int* __restrict__ deg,
                      const int* __restrict__ dst) {
    cudaGridDependencySynchronize();
    int b = blockIdx.x;
    int t = threadIdx.x;
    if (b < NGRAPH) {
        __shared__ float xs[FEAT];
        if (t < FEAT) {
            float acc = b0[t];
            const float* zr = z + b * LATENT;
            #pragma unroll 4
            for (int k = 0; k < LATENT; k++) acc += zr[k] * W0[k * FEAT + t];
            xs[t] = acc > 0.0f ? acc : 0.0f;
        }
        __syncthreads();
        float a = 0.0f;
        #pragma unroll
        for (int k = 0; k < FEAT; k++) a += xs[k] * W1[k * DMODEL + t];
        pg[b * DMODEL + t] = a;
    } else if (b < NGRAPH + NBLK) {
        int i = (b - NGRAPH) * 256 + t;
        int bb = batch[i];
        if (i == 0 || batch[i - 1] != bb) starts[bb] = i;
    } else {
        int e = (b - NGRAPH - NBLK) * 256 + t;
        atomicAdd(&deg[dst[e]], 1);
    }
}

// ---------------- CSR: prefix + local scan + self-loop fill + maxS init --------
__global__ void k_fill2(const int* __restrict__ deg, int* __restrict__ rowptr,
                        int* __restrict__ cursor, int* __restrict__ csrc,
                        float* __restrict__ maxS) {
    cudaGridDependencySynchronize();
    __shared__ int red[256];
    __shared__ int s[256];
    int t = threadIdx.x;
    int b = blockIdx.x;
    if (b == 0 && t < 12) maxS[t] = __int_as_float(0xff800000);  // -inf, 3 slots
    int lim = b * 256;
    int sum = 0;
    for (int i = t; i < lim; i += 256) sum += deg[i] + 1;   // +1 self loop
    red[t] = sum;
    __syncthreads();
    for (int off = 128; off > 0; off >>= 1) {
        if (t < off) red[t] += red[t + off];
        __syncthreads();
    }
    int node = lim + t;
    int d = deg[node] + 1;
    s[t] = d;
    __syncthreads();
    for (int off = 1; off < 256; off <<= 1) {
        int u = (t >= off) ? s[t - off] : 0;
        __syncthreads();
        s[t] += u;
        __syncthreads();
    }
    int r = red[0] + s[t] - d;
    rowptr[node] = r;
    csrc[r] = node;                           // self loop first
    cursor[node] = r + 1;
    if (node == NNODE - 1) rowptr[NNODE] = red[0] + s[t];
}

// ---------------- fused: h1+attn | CSR scatter | deg re-zero --------------------
__global__ void k_mid(const float* __restrict__ pg, const float* __restrict__ W1,
                      const int* __restrict__ batch, const int* __restrict__ starts,
                      const float* __restrict__ attS, const float* __restrict__ attD,
                      float* __restrict__ H, float* __restrict__ aS,
                      float* __restrict__ aD,
                      const int* __restrict__ src, const int* __restrict__ dst,
                      int* __restrict__ cursor, int* __restrict__ csrc,
                      int* __restrict__ deg, float* __restrict__ maxS) {
    cudaGridDependencySynchronize();
    int b = blockIdx.x;
    int tid = threadIdx.x;
    if (b >= WBLK + EBLK) {
        deg[(b - WBLK - EBLK) * 256 + tid] = 0;
        return;
    }
    if (b >= WBLK) {
        int e = (b - WBLK) * 256 + tid;
        int p = atomicAdd(&cursor[dst[e]], 1);
        csrc[p] = src[e];
        return;
    }
    __shared__ float sS[DMODEL], sD[DMODEL];
    __shared__ float sMax[4];
    if (tid < DMODEL) { sS[tid] = attS[tid]; sD[tid] = attD[tid]; }
    if (tid < 4) sMax[tid] = __int_as_float(0xff800000);
    __syncthreads();
    int node = b * 8 + (tid >> 5);
    int lane = tid & 31;
    int g = batch[node];
    int order = node - starts[g];
    int c0 = lane * 8;
    const float4* pgr = (const float4*)(pg + g * DMODEL + c0);
    const float4* w1r = (const float4*)(W1 + (FEAT + order) * DMODEL + c0);
    float4 p0 = pgr[0], p1 = pgr[1];
    float4 w0 = w1r[0], w1v = w1r[1];
    float h[8];
    h[0] = p0.x + w0.x; h[1] = p0.y + w0.y; h[2] = p0.z + w0.z; h[3] = p0.w + w0.w;
    h[4] = p1.x + w1v.x; h[5] = p1.y + w1v.y; h[6] = p1.z + w1v.z; h[7] = p1.w + w1v.w;
    float* hr = H + node * DMODEL + c0;
    *(float4*)hr       = make_float4(h[0], h[1], h[2], h[3]);
    *(float4*)(hr + 4) = make_float4(h[4], h[5], h[6], h[7]);
    float pS = 0.0f, pD = 0.0f;
    #pragma unroll
    for (int j = 0; j < 8; j++) { pS += h[j] * sS[c0 + j]; pD += h[j] * sD[c0 + j]; }
    pS += __shfl_xor_sync(0xffffffffu, pS, 1);
    pS += __shfl_xor_sync(0xffffffffu, pS, 2);
    pS += __shfl_xor_sync(0xffffffffu, pS, 4);
    pD += __shfl_xor_sync(0xffffffffu, pD, 1);
    pD += __shfl_xor_sync(0xffffffffu, pD, 2);
    pD += __shfl_xor_sync(0xffffffffu, pD, 4);
    if ((lane & 7) == 0) {
        int hd = lane >> 3;
        aS[node * 4 + hd] = pS;
        aD[node * 4 + hd] = pD;
        atomicMaxF(&sMax[hd], pS);
    }
    __syncthreads();
    if (tid < 4) atomicMaxF(&maxS[tid], sMax[tid]);
}

// ---------------- tf32 tensor-core GEMM + fused attention logits ---------------
#define SMS 136
__device__ __forceinline__ uint32_t f2tf32(float v) {
    uint32_t r;
    asm("cvt.rna.tf32.f32 %0, %1;" : "=r"(r) : "f"(v));
    return r;
}
__device__ __forceinline__ void mma_tf32(float* c, uint32_t a0, uint32_t a1,
                                         uint32_t a2, uint32_t a3,
                                         uint32_t b0, uint32_t b1) {
    asm volatile(
        "mma.sync.aligned.m16n8k8.row.col.f32.tf32.tf32.f32 "
        "{%0,%1,%2,%3}, {%4,%5,%6,%7}, {%8,%9}, {%0,%1,%2,%3};"
        : "+f"(c[0]), "+f"(c[1]), "+f"(c[2]), "+f"(c[3])
        : "r"(a0), "r"(a1), "r"(a2), "r"(a3), "r"(b0), "r"(b1));
}

__global__ void __launch_bounds__(256, 2)
k_gemm_attn(const float* __restrict__ X, const float* __restrict__ W,
            const float* __restrict__ attS, const float* __restrict__ attD,
            float* __restrict__ C, float* __restrict__ aS, float* __restrict__ aD,
            float* __restrict__ maxS) {
    cudaGridDependencySynchronize();
    __shared__ uint32_t As[32][SMS];
    __shared__ uint32_t Bs[32][SMS];
    __shared__ float sS[128], sD[128];
    __shared__ float sPS[128][2], sPD[128][2];
    __shared__ float sMax[2];

    int tid = threadIdx.x;
    int lane = tid & 31;
    int w = tid >> 5;
    int wm = w & 1, wn = w >> 1;
    int r0 = blockIdx.x * 128;
    int c0 = blockIdx.y * 128;

    if (tid < 128) { sS[tid] = attS[c0 + tid]; sD[tid] = attD[c0 + tid]; }
    if (tid < 2) sMax[tid] = __int_as_float(0xff800000);
    {
        int rr = tid >> 1, hh = tid & 1;
        sPS[rr][hh] = 0.0f;
        sPD[rr][hh] = 0.0f;
    }

    float acc[4][4][4];
    #pragma unroll
    for (int i = 0; i < 4; i++)
        #pragma unroll
        for (int j = 0; j < 4; j++)
            #pragma unroll
            for (int q = 0; q < 4; q++) acc[i][j][q] = 0.0f;

    int am = tid >> 1;
    int ak = (tid & 1) * 16;
    int bkr = tid >> 3;
    int bn = (tid & 7) * 16;

    #pragma unroll 1
    for (int kc = 0; kc < DMODEL; kc += 32) {
        const float4* ap = (const float4*)(X + (r0 + am) * DMODEL + kc + ak);
        #pragma unroll
        for (int q = 0; q < 4; q++) {
            float4 v = ap[q];
            As[ak + q * 4 + 0][am] = f2tf32(v.x);
            As[ak + q * 4 + 1][am] = f2tf32(v.y);
            As[ak + q * 4 + 2][am] = f2tf32(v.z);
            As[ak + q * 4 + 3][am] = f2tf32(v.w);
        }
        const float4* bp = (const float4*)(W + (kc + bkr) * DMODEL + c0 + bn);
        #pragma unroll
        for (int q = 0; q < 4; q++) {
            float4 v = bp[q];
            uint4 u;
            u.x = f2tf32(v.x); u.y = f2tf32(v.y);
            u.z = f2tf32(v.z); u.w = f2tf32(v.w);
            *(uint4*)&Bs[bkr][bn + q * 4] = u;
        }
        __syncthreads();

        #pragma unroll
        for (int kk = 0; kk < 4; kk++) {
            int kb = kk * 8;
            int klo = kb + (lane & 3), khi = klo + 4;
            uint32_t afr[4][4], bfr[4][2];
            #pragma unroll
            for (int mt = 0; mt < 4; mt++) {
                int m = wm * 64 + mt * 16 + (lane >> 2);
                afr[mt][0] = As[klo][m];
                afr[mt][1] = As[klo][m + 8];
                afr[mt][2] = As[khi][m];
                afr[mt][3] = As[khi][m + 8];
            }
            #pragma unroll
            for (int nt = 0; nt < 4; nt++) {
                int n = wn * 32 + nt * 8 + (lane >> 2);
                bfr[nt][0] = Bs[klo][n];
                bfr[nt][1] = Bs[khi][n];
            }
            #pragma unroll
            for (int mt = 0; mt < 4; mt++)
                #pragma unroll
                for (int nt = 0; nt < 4; nt++)
                    mma_tf32(acc[mt][nt], afr[mt][0], afr[mt][1], afr[mt][2],
                             afr[mt][3], bfr[nt][0], bfr[nt][1]);
        }
        __syncthreads();
    }

    int hb = wn >> 1;
    #pragma unroll
    for (int mt = 0; mt < 4; mt++) {
        int rowA = wm * 64 + mt * 16 + (lane >> 2);
        int rowB = rowA + 8;
        float pSa = 0.0f, pDa = 0.0f, pSb = 0.0f, pDb = 0.0f;
        #pragma unroll
        for (int nt = 0; nt < 4; nt++) {
            int lc = wn * 32 + nt * 8 + 2 * (lane & 3);
            float s0 = sS[lc], s1 = sS[lc + 1];
            float d0 = sD[lc], d1 = sD[lc + 1];
            float* a = acc[mt][nt];
            pSa += a[0] * s0 + a[1] * s1;
            pDa += a[0] * d0 + a[1] * d1;
            pSb += a[2] * s0 + a[3] * s1;
            pDb += a[2] * d0 + a[3] * d1;
            float* cpA = C + (r0 + rowA) * DMODEL + c0 + lc;
            float* cpB = C + (r0 + rowB) * DMODEL + c0 + lc;
            *(float2*)cpA = make_float2(a[0], a[1]);
            *(float2*)cpB = make_float2(a[2], a[3]);
        }
        pSa += __shfl_xor_sync(0xffffffffu, pSa, 1);
        pSa += __shfl_xor_sync(0xffffffffu, pSa, 2);
        pDa += __shfl_xor_sync(0xffffffffu, pDa, 1);
        pDa += __shfl_xor_sync(0xffffffffu, pDa, 2);
        pSb += __shfl_xor_sync(0xffffffffu, pSb, 1);
        pSb += __shfl_xor_sync(0xffffffffu, pSb, 2);
        pDb += __shfl_xor_sync(0xffffffffu, pDb, 1);
        pDb += __shfl_xor_sync(0xffffffffu, pDb, 2);
        if ((lane & 3) == 0) {
            atomicAdd(&sPS[rowA][hb], pSa);
            atomicAdd(&sPD[rowA][hb], pDa);
            atomicAdd(&sPS[rowB][hb], pSb);
            atomicAdd(&sPD[rowB][hb], pDb);
        }
    }
    __syncthreads();
    {
        int rr = tid >> 1, hh = tid & 1;
        int node = r0 + rr;
        int head = blockIdx.y * 2 + hh;
        float v = sPS[rr][hh];
        aS[node * 4 + head] = v;
        aD[node * 4 + head] = sPD[rr][hh];
        atomicMaxF(&sMax[hh], v);
    }
    __syncthreads();
    if (tid < 2) atomicMaxF(&maxS[blockIdx.y * 2 + tid], sMax[tid]);
}

// ---------------- segment softmax + weighted aggregate --------------------------
__device__ __forceinline__ float lrelu(float v) { return v > 0.0f ? v : 0.2f * v; }

__device__ __forceinline__ void aggregate_node(
    int node, int lane, const int* __restrict__ rowptr, const int* __restrict__ csrc,
    const float* __restrict__ H, const float* __restrict__ aS,
    const float* __restrict__ aD, const float* __restrict__ bias,
    const float* __restrict__ maxS, float* __restrict__ ex, float r[8]) {
    int rs = rowptr[node], re = rowptr[node + 1];
    float4 ad = *(const float4*)(aD + node * 4);
    float4 mx = *(const float4*)maxS;
    float b0v = lrelu(mx.x + ad.x);
    float b1v = lrelu(mx.y + ad.y);
    float b2v = lrelu(mx.z + ad.z);
    float b3v = lrelu(mx.w + ad.w);

    float s0 = 0, s1 = 0, s2 = 0, s3 = 0;
    for (int e = rs + lane; e < re; e += 32) {
        int s = csrc[e];
        float4 as = *(const float4*)(aS + s * 4);
        float x0 = expf(lrelu(as.x + ad.x) - b0v);
        float x1 = expf(lrelu(as.y + ad.y) - b1v);
        float x2 = expf(lrelu(as.z + ad.z) - b2v);
        float x3 = expf(lrelu(as.w + ad.w) - b3v);
        *(float4*)(ex + e * 4) = make_float4(x0, x1, x2, x3);
        s0 += x0; s1 += x1; s2 += x2; s3 += x3;
    }
    #pragma unroll
    for (int o = 16; o > 0; o >>= 1) {
        s0 += __shfl_xor_sync(0xffffffffu, s0, o);
        s1 += __shfl_xor_sync(0xffffffffu, s1, o);
        s2 += __shfl_xor_sync(0xffffffffu, s2, o);
        s3 += __shfl_xor_sync(0xffffffffu, s3, o);
    }
    int head = lane >> 3;
    float sh = head == 0 ? s0 : head == 1 ? s1 : head == 2 ? s2 : s3;
    float inv = 1.0f / (sh + 1e-16f);

    float acc[8] = {};
    int cb = lane * 8;
    int sNext = csrc[rs];
    for (int e = rs; e < re; e++) {
        int s = sNext;
        if (e + 1 < re) sNext = csrc[e + 1];
        float xv = __ldg(ex + e * 4 + head);
        const float4* hp = (const float4*)(H + s * DMODEL + cb);
        float4 h0 = hp[0], h1 = hp[1];
        acc[0] += xv * h0.x; acc[1] += xv * h0.y;
        acc[2] += xv * h0.z; acc[3] += xv * h0.w;
        acc[4] += xv * h1.x; acc[5] += xv * h1.y;
        acc[6] += xv * h1.z; acc[7] += xv * h1.w;
    }
    const float4* bp = (const float4*)(bias + cb);
    float4 b0 = bp[0], b1 = bp[1];
    r[0] = acc[0] * inv + b0.x; r[1] = acc[1] * inv + b0.y;
    r[2] = acc[2] * inv + b0.z; r[3] = acc[3] * inv + b0.w;
    r[4] = acc[4] * inv + b1.x; r[5] = acc[5] * inv + b1.y;
    r[6] = acc[6] * inv + b1.z; r[7] = acc[7] * inv + b1.w;
    #pragma unroll
    for (int i = 0; i < 8; i++) r[i] = r[i] > 0.0f ? r[i] : 0.0f;
}

__global__ void k_aggregate(const int* __restrict__ rowptr, const int* __restrict__ csrc,
                            const float* __restrict__ H, const float* __restrict__ aS,
                            const float* __restrict__ aD, const float* __restrict__ bias,
                            const float* __restrict__ maxS,
                            float* __restrict__ ex, float* __restrict__ out) {
    cudaGridDependencySynchronize();
    int node = (blockIdx.x * blockDim.x + threadIdx.x) >> 5;
    int lane = threadIdx.x & 31;
    if (node >= NNODE) return;
    float r[8];
    aggregate_node(node, lane, rowptr, csrc, H, aS, aD, bias, maxS, ex, r);
    float* op = out + node * DMODEL + lane * 8;
    *(float4*)op       = make_float4(r[0], r[1], r[2], r[3]);
    *(float4*)(op + 4) = make_float4(r[4], r[5], r[6], r[7]);
}

// ---------------- fused: layer-3 aggregate + dec_geo + fc_geo ------------------
// 32 nodes per block (4 per warp): Wg streamed once per 32 nodes (38 MB total).
__global__ void __launch_bounds__(256)
k_agg_final(const int* __restrict__ rowptr, const int* __restrict__ csrc,
            const float* __restrict__ H, const float* __restrict__ aS,
            const float* __restrict__ aD, const float* __restrict__ bias,
            const float* __restrict__ maxS, float* __restrict__ ex,
            const float* __restrict__ Wg, const float* __restrict__ bg,
            const float* __restrict__ Wf, const float* __restrict__ bf,
            float* __restrict__ out) {
    cudaGridDependencySynchronize();
    __shared__ float sWg[64][FEAT];           // 16 KB chunk of Wg (64 K-rows)
    __shared__ float sx[32][DMODEL];          // 32 KB node features
    __shared__ float sWf[FEAT * 5];

    int tid = threadIdx.x;
    int w = tid >> 5;
    int lane = tid & 31;
    int node0 = blockIdx.x * 32 + w * 4;

    for (int i = tid; i < FEAT * 5; i += 256) sWf[i] = Wf[i];

    float r[8];
    #pragma unroll
    for (int j = 0; j < 4; j++) {
        aggregate_node(node0 + j, lane, rowptr, csrc, H, aS, aD, bias, maxS, ex, r);
        float* sxp = &sx[w * 4 + j][lane * 8];
        *(float4*)sxp       = make_float4(r[0], r[1], r[2], r[3]);
        *(float4*)(sxp + 4) = make_float4(r[4], r[5], r[6], r[7]);
    }
    __syncthreads();

    // y for 4 nodes; thread owns columns lane and lane+32
    float bgl = bg[lane], bgh = bg[lane + 32];
    float y0[4], y1[4];
    #pragma unroll
    for (int j = 0; j < 4; j++) { y0[j] = bgl; y1[j] = bgh; }
    #pragma unroll 1
    for (int kc = 0; kc < DMODEL; kc += 64) {
        // stage 64x64 chunk of Wg (4096 floats, float4 granularity)
        #pragma unroll
        for (int t2 = 0; t2 < 4; t2++) {
            int idx = (tid + t2 * 256) * 4;
            *(float4*)&sWg[idx >> 6][idx & 63] =
                *(const float4*)(Wg + kc * FEAT + idx);
        }
        __syncthreads();
        #pragma unroll 4
        for (int k = 0; k < 64; k++) {
            float wv0 = sWg[k][lane];
            float wv1 = sWg[k][lane + 32];
            #pragma unroll
            for (int j = 0; j < 4; j++) {
                float xv = sx[w * 4 + j][kc + k];
                y0[j] += xv * wv0;
                y1[j] += xv * wv1;
            }
        }
        __syncthreads();
    }
    #pragma unroll
    for (int j = 0; j < 4; j++) {
        y0[j] = y0[j] > 0.0f ? y0[j] : 0.0f;
        y1[j] = y1[j] > 0.0f ? y1[j] : 0.0f;
    }

    // out[node][c] = bf[c] + y0*Wf[lane] + y1*Wf[lane+32], reduced over warp
    float p[4][5];
    #pragma unroll
    for (int c = 0; c < 5; c++) {
        float w0 = sWf[lane * 5 + c], w1 = sWf[(lane + 32) * 5 + c];
        #pragma unroll
        for (int j = 0; j < 4; j++)
            p[j][c] = y0[j] * w0 + y1[j] * w1;
    }
    #pragma unroll
    for (int o = 16; o > 0; o >>= 1) {
        #pragma unroll
        for (int j = 0; j < 4; j++)
            #pragma unroll
            for (int c = 0; c < 5; c++)
                p[j][c] += __shfl_xor_sync(0xffffffffu, p[j][c], o);
    }
    if (lane == 0) {
        #pragma unroll
        for (int j = 0; j < 4; j++)
            #pragma unroll
            for (int c = 0; c < 5; c++)
                out[(node0 + j) * 5 + c] = p[j][c] + bf[c];
    }
}

// ---------------- host: PDL launch helper --------------------------------------
static inline void launch_pdl(const void* func, dim3 grid, dim3 block, void** args) {
    cudaLaunchConfig_t cfg = {};
    cfg.gridDim = grid;
    cfg.blockDim = block;
    cfg.dynamicSmemBytes = 0;
    cfg.stream = 0;
    cudaLaunchAttribute attr[1];
    attr[0].id = cudaLaunchAttributeProgrammaticStreamSerialization;
    attr[0].val.programmaticStreamSerializationAllowed = 1;
    cfg.attrs = attr;
    cfg.numAttrs = 1;
    cudaLaunchKernelExC(&cfg, func, args);
}

// ---------------- host orchestration ------------------------------------------
extern "C" void kernel_launch(void* const* d_in, const int* in_sizes, int n_in,
                              void* d_out, int out_size) {
    const float* z     = (const float*)d_in[0];
    const int*   ei    = (const int*)d_in[1];
    const int*   batch = (const int*)d_in[2];
    int base = (in_sizes[3] == 1) ? 4 : 3;
    const float* W0  = (const float*)d_in[base + 0];
    const float* b0  = (const float*)d_in[base + 1];
    const float* W1  = (const float*)d_in[base + 2];
    const float* as1 = (const float*)d_in[base + 3];
    const float* ad1 = (const float*)d_in[base + 4];
    const float* bb1 = (const float*)d_in[base + 5];
    const float* W2  = (const float*)d_in[base + 6];
    const float* as2 = (const float*)d_in[base + 7];
    const float* ad2 = (const float*)d_in[base + 8];
    const float* bb2 = (const float*)d_in[base + 9];
    const float* W3  = (const float*)d_in[base + 10];
    const float* as3 = (const float*)d_in[base + 11];
    const float* ad3 = (const float*)d_in[base + 12];
    const float* bb3 = (const float*)d_in[base + 13];
    const float* Wg  = (const float*)d_in[base + 14];
    const float* bg  = (const float*)d_in[base + 15];
    const float* Wf  = (const float*)d_in[base + 16];
    const float* bf  = (const float*)d_in[base + 17];

    const int* srcArr = ei;
    const int* dstArr = ei + NEDGE;

    float *bufA, *bufB, *aS, *aD, *exB, *pgB, *maxB;
    int *startsB, *degB, *rowptrB, *cursorB, *csrcB;
    cudaGetSymbolAddress((void**)&bufA, g_bufA);
    cudaGetSymbolAddress((void**)&bufB, g_bufB);
    cudaGetSymbolAddress((void**)&aS, g_as);
    cudaGetSymbolAddress((void**)&aD, g_ad);
    cudaGetSymbolAddress((void**)&exB, g_ex);
    cudaGetSymbolAddress((void**)&pgB, g_pg);
    cudaGetSymbolAddress((void**)&maxB, g_maxS);
    cudaGetSymbolAddress((void**)&startsB, g_starts);
    cudaGetSymbolAddress((void**)&degB, g_deg);
    cudaGetSymbolAddress((void**)&rowptrB, g_rowptr);
    cudaGetSymbolAddress((void**)&cursorB, g_cursor);
    cudaGetSymbolAddress((void**)&csrcB, g_csrc);

    float* max0 = maxB;
    float* max1 = maxB + 4;
    float* max2 = maxB + 8;
    float* outP = (float*)d_out;

    {   // 1: prologue
        void* a[] = {&z, &W0, &b0, &W1, &pgB, &batch, &startsB, &degB, &dstArr};
        launch_pdl((const void*)k_pro, dim3(NGRAPH + NBLK + EBLK), dim3(256), a);
    }
    {   // 2: CSR rowptr + fill
        void* a[] = {&degB, &rowptrB, &cursorB, &csrcB, &maxB};
        launch_pdl((const void*)k_fill2, dim3(NBLK), dim3(256), a);
    }
    {   // 3: h1+attn | scatter | deg re-zero
        void* a[] = {&pgB, &W1, &batch, &startsB, &as1, &ad1, &bufB, &aS, &aD,
                     &srcArr, &dstArr, &cursorB, &csrcB, &degB, &max0};
        launch_pdl((const void*)k_mid, dim3(WBLK + EBLK + NBLK), dim3(256), a);
    }
    {   // 4: aggregate layer 1
        void* a[] = {&rowptrB, &csrcB, &bufB, &aS, &aD, &bb1, &max0, &exB, &bufA};
        launch_pdl((const void*)k_aggregate, dim3(WBLK), dim3(256), a);
    }
    {   // 5: layer-2 GEMM
        void* a[] = {&bufA, &W2, &as2, &ad2, &bufB, &aS, &aD, &max1};
        launch_pdl((const void*)k_gemm_attn, dim3(NNODE / 128, 2), dim3(256), a);
    }
    {   // 6: aggregate layer 2
        void* a[] = {&rowptrB, &csrcB, &bufB, &aS, &aD, &bb2, &max1, &exB, &bufA};
        launch_pdl((const void*)k_aggregate, dim3(WBLK), dim3(256), a);
    }
    {   // 7: layer-3 GEMM
        void* a[] = {&bufA, &W3, &as3, &ad3, &bufB, &aS, &aD, &max2};
        launch_pdl((const void*)k_gemm_attn, dim3(NNODE / 128, 2), dim3(256), a);
    }
    {   // 8: layer-3 aggregate fused with dec_geo + fc_geo (32 nodes/block)
        void* a[] = {&rowptrB, &csrcB, &bufB, &aS, &aD, &bb3, &max2, &exB,
                     &Wg, &bg, &Wf, &bf, &outP};
        launch_pdl((const void*)k_agg_final, dim3(AFBLK), dim3(256), a);
    }
}

// round 17
// speedup vs baseline: 1.2713x; 1.0168x over previous
#include <cuda_runtime.h>
#include <math.h>
#include <stdint.h>

// ---------------- problem constants -----------------------------------------
#define NNODE 19200
#define NEDGE 230400
#define NGRAPH 128
#define LATENT 256
#define FEAT 64
#define HEADS 4
#define POS 180
#define DMODEL 256       // HEADS * FEAT
#define ETOT (NEDGE + NNODE)
#define NBLK 75          // NNODE / 256
#define EBLK 900         // NEDGE / 256
#define WBLK 2400        // NNODE / 8 (8 warps per block)
#define AFBLK 300        // NNODE / 64 (k_agg_final: 64 nodes/block, 512 thr)

// ---------------- static device scratch --------------------------------------
__device__ __align__(16) float g_bufA[NNODE * DMODEL];
__device__ __align__(16) float g_bufB[NNODE * DMODEL];
__device__ __align__(16) float g_as[NNODE * HEADS];
__device__ __align__(16) float g_ad[NNODE * HEADS];
__device__ __align__(16) float g_ex[ETOT * HEADS];
__device__ __align__(16) float g_pg[NGRAPH * DMODEL];
__device__ __align__(16) float g_maxS[3][4];   // per-layer global aS max (slots)
__device__ int g_starts[NGRAPH];
__device__ int g_deg[NNODE];      // zero at load; re-zeroed each replay in k_mid
__device__ int g_rowptr[NNODE + 1];
__device__ int g_cursor[NNODE];
__device__ int g_csrc[ETOT];

__device__ __forceinline__ void atomicMaxF(float* a, float v) {
    if (v >= 0.0f) atomicMax((int*)a, __float_as_int(v));
    else           atomicMin((unsigned int*)a, __float_as_uint(v));
}

// ---------------- fused prologue: x0pg | starts | hist -------------------------
__global__ void k_pro(const float* __restrict__ z, const float* __restrict__ W0,
                      const float* __restrict__ b0, const float* __restrict__ W1,
                      float* __restrict__ pg, const int* __restrict__ batch,
                      int* __restrict__ starts, int* __restrict__ deg,
                      const int* __restrict__ dst) {
    cudaGridDependencySynchronize();
    int b = blockIdx.x;
    int t = threadIdx.x;
    if (b < NGRAPH) {
        __shared__ float xs[FEAT];
        if (t < FEAT) {
            float acc = b0[t];
            const float* zr = z + b * LATENT;
            #pragma unroll 4
            for (int k = 0; k < LATENT; k++) acc += zr[k] * W0[k * FEAT + t];
            xs[t] = acc > 0.0f ? acc : 0.0f;
        }
        __syncthreads();
        float a = 0.0f;
        #pragma unroll
        for (int k = 0; k < FEAT; k++) a += xs[k] * W1[k * DMODEL + t];
        pg[b * DMODEL + t] = a;
    } else if (b < NGRAPH + NBLK) {
        int i = (b - NGRAPH) * 256 + t;
        int bb = batch[i];
        if (i == 0 || batch[i - 1] != bb) starts[bb] = i;
    } else {
        int e = (b - NGRAPH - NBLK) * 256 + t;
        atomicAdd(&deg[dst[e]], 1);
    }
}

// ---------------- CSR: prefix + local scan + self-loop fill + maxS init --------
__global__ void k_fill2(const int* __restrict__ deg, int* __restrict__ rowptr,
                        int* __restrict__ cursor, int* __restrict__ csrc,
                        float* __restrict__ maxS) {
    cudaGridDependencySynchronize();
    __shared__ int red[256];
    __shared__ int s[256];
    int t = threadIdx.x;
    int b = blockIdx.x;
    if (b == 0 && t < 12) maxS[t] = __int_as_float(0xff800000);  // -inf, 3 slots
    int lim = b * 256;
    int sum = 0;
    for (int i = t; i < lim; i += 256) sum += deg[i] + 1;   // +1 self loop
    red[t] = sum;
    __syncthreads();
    for (int off = 128; off > 0; off >>= 1) {
        if (t < off) red[t] += red[t + off];
        __syncthreads();
    }
    int node = lim + t;
    int d = deg[node] + 1;
    s[t] = d;
    __syncthreads();
    for (int off = 1; off < 256; off <<= 1) {
        int u = (t >= off) ? s[t - off] : 0;
        __syncthreads();
        s[t] += u;
        __syncthreads();
    }
    int r = red[0] + s[t] - d;
    rowptr[node] = r;
    csrc[r] = node;                           // self loop first
    cursor[node] = r + 1;
    if (node == NNODE - 1) rowptr[NNODE] = red[0] + s[t];
}

// ---------------- fused: h1+attn | CSR scatter | deg re-zero --------------------
__global__ void k_mid(const float* __restrict__ pg, const float* __restrict__ W1,
                      const int* __restrict__ batch, const int* __restrict__ starts,
                      const float* __restrict__ attS, const float* __restrict__ attD,
                      float* __restrict__ H, float* __restrict__ aS,
                      float* __restrict__ aD,
                      const int* __restrict__ src, const int* __restrict__ dst,
                      int* __restrict__ cursor, int* __restrict__ csrc,
                      int* __restrict__ deg, float* __restrict__ maxS) {
    cudaGridDependencySynchronize();
    int b = blockIdx.x;
    int tid = threadIdx.x;
    if (b >= WBLK + EBLK) {
        deg[(b - WBLK - EBLK) * 256 + tid] = 0;
        return;
    }
    if (b >= WBLK) {
        int e = (b - WBLK) * 256 + tid;
        int p = atomicAdd(&cursor[dst[e]], 1);
        csrc[p] = src[e];
        return;
    }
    __shared__ float sS[DMODEL], sD[DMODEL];
    __shared__ float sMax[4];
    if (tid < DMODEL) { sS[tid] = attS[tid]; sD[tid] = attD[tid]; }
    if (tid < 4) sMax[tid] = __int_as_float(0xff800000);
    __syncthreads();
    int node = b * 8 + (tid >> 5);
    int lane = tid & 31;
    int g = batch[node];
    int order = node - starts[g];
    int c0 = lane * 8;
    const float4* pgr = (const float4*)(pg + g * DMODEL + c0);
    const float4* w1r = (const float4*)(W1 + (FEAT + order) * DMODEL + c0);
    float4 p0 = pgr[0], p1 = pgr[1];
    float4 w0 = w1r[0], w1v = w1r[1];
    float h[8];
    h[0] = p0.x + w0.x; h[1] = p0.y + w0.y; h[2] = p0.z + w0.z; h[3] = p0.w + w0.w;
    h[4] = p1.x + w1v.x; h[5] = p1.y + w1v.y; h[6] = p1.z + w1v.z; h[7] = p1.w + w1v.w;
    float* hr = H + node * DMODEL + c0;
    *(float4*)hr       = make_float4(h[0], h[1], h[2], h[3]);
    *(float4*)(hr + 4) = make_float4(h[4], h[5], h[6], h[7]);
    float pS = 0.0f, pD = 0.0f;
    #pragma unroll
    for (int j = 0; j < 8; j++) { pS += h[j] * sS[c0 + j]; pD += h[j] * sD[c0 + j]; }
    pS += __shfl_xor_sync(0xffffffffu, pS, 1);
    pS += __shfl_xor_sync(0xffffffffu, pS, 2);
    pS += __shfl_xor_sync(0xffffffffu, pS, 4);
    pD += __shfl_xor_sync(0xffffffffu, pD, 1);
    pD += __shfl_xor_sync(0xffffffffu, pD, 2);
    pD += __shfl_xor_sync(0xffffffffu, pD, 4);
    if ((lane & 7) == 0) {
        int hd = lane >> 3;
        aS[node * 4 + hd] = pS;
        aD[node * 4 + hd] = pD;
        atomicMaxF(&sMax[hd], pS);
    }
    __syncthreads();
    if (tid < 4) atomicMaxF(&maxS[tid], sMax[tid]);
}

// ---------------- tf32 tensor-core GEMM + fused attention logits ---------------
#define SMS 136
__device__ __forceinline__ uint32_t f2tf32(float v) {
    uint32_t r;
    asm("cvt.rna.tf32.f32 %0, %1;" : "=r"(r) : "f"(v));
    return r;
}
__device__ __forceinline__ void mma_tf32(float* c, uint32_t a0, uint32_t a1,
                                         uint32_t a2, uint32_t a3,
                                         uint32_t b0, uint32_t b1) {
    asm volatile(
        "mma.sync.aligned.m16n8k8.row.col.f32.tf32.tf32.f32 "
        "{%0,%1,%2,%3}, {%4,%5,%6,%7}, {%8,%9}, {%0,%1,%2,%3};"
        : "+f"(c[0]), "+f"(c[1]), "+f"(c[2]), "+f"(c[3])
        : "r"(a0), "r"(a1), "r"(a2), "r"(a3), "r"(b0), "r"(b1));
}

__global__ void __launch_bounds__(256, 2)
k_gemm_attn(const float* __restrict__ X, const float* __restrict__ W,
            const float* __restrict__ attS, const float* __restrict__ attD,
            float* __restrict__ C, float* __restrict__ aS, float* __restrict__ aD,
            float* __restrict__ maxS) {
    cudaGridDependencySynchronize();
    __shared__ uint32_t As[32][SMS];
    __shared__ uint32_t Bs[32][SMS];
    __shared__ float sS[128], sD[128];
    __shared__ float sPS[128][2], sPD[128][2];
    __shared__ float sMax[2];

    int tid = threadIdx.x;
    int lane = tid & 31;
    int w = tid >> 5;
    int wm = w & 1, wn = w >> 1;
    int r0 = blockIdx.x * 128;
    int c0 = blockIdx.y * 128;

    if (tid < 128) { sS[tid] = attS[c0 + tid]; sD[tid] = attD[c0 + tid]; }
    if (tid < 2) sMax[tid] = __int_as_float(0xff800000);
    {
        int rr = tid >> 1, hh = tid & 1;
        sPS[rr][hh] = 0.0f;
        sPD[rr][hh] = 0.0f;
    }

    float acc[4][4][4];
    #pragma unroll
    for (int i = 0; i < 4; i++)
        #pragma unroll
        for (int j = 0; j < 4; j++)
            #pragma unroll
            for (int q = 0; q < 4; q++) acc[i][j][q] = 0.0f;

    int am = tid >> 1;
    int ak = (tid & 1) * 16;
    int bkr = tid >> 3;
    int bn = (tid & 7) * 16;

    #pragma unroll 1
    for (int kc = 0; kc < DMODEL; kc += 32) {
        const float4* ap = (const float4*)(X + (r0 + am) * DMODEL + kc + ak);
        #pragma unroll
        for (int q = 0; q < 4; q++) {
            float4 v = ap[q];
            As[ak + q * 4 + 0][am] = f2tf32(v.x);
            As[ak + q * 4 + 1][am] = f2tf32(v.y);
            As[ak + q * 4 + 2][am] = f2tf32(v.z);
            As[ak + q * 4 + 3][am] = f2tf32(v.w);
        }
        const float4* bp = (const float4*)(W + (kc + bkr) * DMODEL + c0 + bn);
        #pragma unroll
        for (int q = 0; q < 4; q++) {
            float4 v = bp[q];
            uint4 u;
            u.x = f2tf32(v.x); u.y = f2tf32(v.y);
            u.z = f2tf32(v.z); u.w = f2tf32(v.w);
            *(uint4*)&Bs[bkr][bn + q * 4] = u;
        }
        __syncthreads();

        #pragma unroll
        for (int kk = 0; kk < 4; kk++) {
            int kb = kk * 8;
            int klo = kb + (lane & 3), khi = klo + 4;
            uint32_t afr[4][4], bfr[4][2];
            #pragma unroll
            for (int mt = 0; mt < 4; mt++) {
                int m = wm * 64 + mt * 16 + (lane >> 2);
                afr[mt][0] = As[klo][m];
                afr[mt][1] = As[klo][m + 8];
                afr[mt][2] = As[khi][m];
                afr[mt][3] = As[khi][m + 8];
            }
            #pragma unroll
            for (int nt = 0; nt < 4; nt++) {
                int n = wn * 32 + nt * 8 + (lane >> 2);
                bfr[nt][0] = Bs[klo][n];
                bfr[nt][1] = Bs[khi][n];
            }
            #pragma unroll
            for (int mt = 0; mt < 4; mt++)
                #pragma unroll
                for (int nt = 0; nt < 4; nt++)
                    mma_tf32(acc[mt][nt], afr[mt][0], afr[mt][1], afr[mt][2],
                             afr[mt][3], bfr[nt][0], bfr[nt][1]);
        }
        __syncthreads();
    }

    int hb = wn >> 1;
    #pragma unroll
    for (int mt = 0; mt < 4; mt++) {
        int rowA = wm * 64 + mt * 16 + (lane >> 2);
        int rowB = rowA + 8;
        float pSa = 0.0f, pDa = 0.0f, pSb = 0.0f, pDb = 0.0f;
        #pragma unroll
        for (int nt = 0; nt < 4; nt++) {
            int lc = wn * 32 + nt * 8 + 2 * (lane & 3);
            float s0 = sS[lc], s1 = sS[lc + 1];
            float d0 = sD[lc], d1 = sD[lc + 1];
            float* a = acc[mt][nt];
            pSa += a[0] * s0 + a[1] * s1;
            pDa += a[0] * d0 + a[1] * d1;
            pSb += a[2] * s0 + a[3] * s1;
            pDb += a[2] * d0 + a[3] * d1;
            float* cpA = C + (r0 + rowA) * DMODEL + c0 + lc;
            float* cpB = C + (r0 + rowB) * DMODEL + c0 + lc;
            *(float2*)cpA = make_float2(a[0], a[1]);
            *(float2*)cpB = make_float2(a[2], a[3]);
        }
        pSa += __shfl_xor_sync(0xffffffffu, pSa, 1);
        pSa += __shfl_xor_sync(0xffffffffu, pSa, 2);
        pDa += __shfl_xor_sync(0xffffffffu, pDa, 1);
        pDa += __shfl_xor_sync(0xffffffffu, pDa, 2);
        pSb += __shfl_xor_sync(0xffffffffu, pSb, 1);
        pSb += __shfl_xor_sync(0xffffffffu, pSb, 2);
        pDb += __shfl_xor_sync(0xffffffffu, pDb, 1);
        pDb += __shfl_xor_sync(0xffffffffu, pDb, 2);
        if ((lane & 3) == 0) {
            atomicAdd(&sPS[rowA][hb], pSa);
            atomicAdd(&sPD[rowA][hb], pDa);
            atomicAdd(&sPS[rowB][hb], pSb);
            atomicAdd(&sPD[rowB][hb], pDb);
        }
    }
    __syncthreads();
    {
        int rr = tid >> 1, hh = tid & 1;
        int node = r0 + rr;
        int head = blockIdx.y * 2 + hh;
        float v = sPS[rr][hh];
        aS[node * 4 + head] = v;
        aD[node * 4 + head] = sPD[rr][hh];
        atomicMaxF(&sMax[hh], v);
    }
    __syncthreads();
    if (tid < 2) atomicMaxF(&maxS[blockIdx.y * 2 + tid], sMax[tid]);
}

// ---------------- segment softmax + weighted aggregate --------------------------
__device__ __forceinline__ float lrelu(float v) { return v > 0.0f ? v : 0.2f * v; }

__device__ __forceinline__ void aggregate_node(
    int node, int lane, const int* __restrict__ rowptr, const int* __restrict__ csrc,
    const float* __restrict__ H, const float* __restrict__ aS,
    const float* __restrict__ aD, const float* __restrict__ bias,
    const float* __restrict__ maxS, float* __restrict__ ex, float r[8]) {
    int rs = rowptr[node], re = rowptr[node + 1];
    float4 ad = *(const float4*)(aD + node * 4);
    float4 mx = *(const float4*)maxS;
    float b0v = lrelu(mx.x + ad.x);
    float b1v = lrelu(mx.y + ad.y);
    float b2v = lrelu(mx.z + ad.z);
    float b3v = lrelu(mx.w + ad.w);

    float s0 = 0, s1 = 0, s2 = 0, s3 = 0;
    for (int e = rs + lane; e < re; e += 32) {
        int s = csrc[e];
        float4 as = *(const float4*)(aS + s * 4);
        float x0 = expf(lrelu(as.x + ad.x) - b0v);
        float x1 = expf(lrelu(as.y + ad.y) - b1v);
        float x2 = expf(lrelu(as.z + ad.z) - b2v);
        float x3 = expf(lrelu(as.w + ad.w) - b3v);
        *(float4*)(ex + e * 4) = make_float4(x0, x1, x2, x3);
        s0 += x0; s1 += x1; s2 += x2; s3 += x3;
    }
    #pragma unroll
    for (int o = 16; o > 0; o >>= 1) {
        s0 += __shfl_xor_sync(0xffffffffu, s0, o);
        s1 += __shfl_xor_sync(0xffffffffu, s1, o);
        s2 += __shfl_xor_sync(0xffffffffu, s2, o);
        s3 += __shfl_xor_sync(0xffffffffu, s3, o);
    }
    int head = lane >> 3;
    float sh = head == 0 ? s0 : head == 1 ? s1 : head == 2 ? s2 : s3;
    float inv = 1.0f / (sh + 1e-16f);

    float acc[8] = {};
    int cb = lane * 8;
    int sNext = csrc[rs];
    for (int e = rs; e < re; e++) {
        int s = sNext;
        if (e + 1 < re) sNext = csrc[e + 1];
        float xv = __ldg(ex + e * 4 + head);
        const float4* hp = (const float4*)(H + s * DMODEL + cb);
        float4 h0 = hp[0], h1 = hp[1];
        acc[0] += xv * h0.x; acc[1] += xv * h0.y;
        acc[2] += xv * h0.z; acc[3] += xv * h0.w;
        acc[4] += xv * h1.x; acc[5] += xv * h1.y;
        acc[6] += xv * h1.z; acc[7] += xv * h1.w;
    }
    const float4* bp = (const float4*)(bias + cb);
    float4 b0 = bp[0], b1 = bp[1];
    r[0] = acc[0] * inv + b0.x; r[1] = acc[1] * inv + b0.y;
    r[2] = acc[2] * inv + b0.z; r[3] = acc[3] * inv + b0.w;
    r[4] = acc[4] * inv + b1.x; r[5] = acc[5] * inv + b1.y;
    r[6] = acc[6] * inv + b1.z; r[7] = acc[7] * inv + b1.w;
    #pragma unroll
    for (int i = 0; i < 8; i++) r[i] = r[i] > 0.0f ? r[i] : 0.0f;
}

__global__ void k_aggregate(const int* __restrict__ rowptr, const int* __restrict__ csrc,
                            const float* __restrict__ H, const float* __restrict__ aS,
                            const float* __restrict__ aD, const float* __restrict__ bias,
                            const float* __restrict__ maxS,
                            float* __restrict__ ex, float* __restrict__ out) {
    cudaGridDependencySynchronize();
    int node = (blockIdx.x * blockDim.x + threadIdx.x) >> 5;
    int lane = threadIdx.x & 31;
    if (node >= NNODE) return;
    float r[8];
    aggregate_node(node, lane, rowptr, csrc, H, aS, aD, bias, maxS, ex, r);
    float* op = out + node * DMODEL + lane * 8;
    *(float4*)op       = make_float4(r[0], r[1], r[2], r[3]);
    *(float4*)(op + 4) = make_float4(r[4], r[5], r[6], r[7]);
}

// ---------------- fused: layer-3 aggregate + dec_geo + fc_geo ------------------
// 64 nodes per block, 512 threads (4 nodes/warp): Wg streamed once per 64 nodes.
__global__ void __launch_bounds__(512)
k_agg_final(const int* __restrict__ rowptr, const int* __restrict__ csrc,
            const float* __restrict__ H, const float* __restrict__ aS,
            const float* __restrict__ aD, const float* __restrict__ bias,
            const float* __restrict__ maxS, float* __restrict__ ex,
            const float* __restrict__ Wg, const float* __restrict__ bg,
            const float* __restrict__ Wf, const float* __restrict__ bf,
            float* __restrict__ out) {
    cudaGridDependencySynchronize();
    __shared__ float sWg[64][FEAT];           // 16 KB chunk of Wg (64 K-rows)
    __shared__ float sx[64][DMODEL];          // 64 KB node features
    __shared__ float sWf[FEAT * 5];

    int tid = threadIdx.x;
    int w = tid >> 5;                         // 0..15
    int lane = tid & 31;
    int node0 = blockIdx.x * 64 + w * 4;

    for (int i = tid; i < FEAT * 5; i += 512) sWf[i] = Wf[i];

    float r[8];
    #pragma unroll
    for (int j = 0; j < 4; j++) {
        aggregate_node(node0 + j, lane, rowptr, csrc, H, aS, aD, bias, maxS, ex, r);
        float* sxp = &sx[w * 4 + j][lane * 8];
        *(float4*)sxp       = make_float4(r[0], r[1], r[2], r[3]);
        *(float4*)(sxp + 4) = make_float4(r[4], r[5], r[6], r[7]);
    }
    __syncthreads();

    // y for 4 nodes; thread owns columns lane and lane+32
    float bgl = bg[lane], bgh = bg[lane + 32];
    float y0[4], y1[4];
    #pragma unroll
    for (int j = 0; j < 4; j++) { y0[j] = bgl; y1[j] = bgh; }
    #pragma unroll 1
    for (int kc = 0; kc < DMODEL; kc += 64) {
        // stage 64x64 chunk of Wg (4096 floats, 512 threads x float4 x 2)
        #pragma unroll
        for (int t2 = 0; t2 < 2; t2++) {
            int idx = (tid + t2 * 512) * 4;
            *(float4*)&sWg[idx >> 6][idx & 63] =
                *(const float4*)(Wg + kc * FEAT + idx);
        }
        __syncthreads();
        #pragma unroll 4
        for (int k = 0; k < 64; k++) {
            float wv0 = sWg[k][lane];
            float wv1 = sWg[k][lane + 32];
            #pragma unroll
            for (int j = 0; j < 4; j++) {
                float xv = sx[w * 4 + j][kc + k];
                y0[j] += xv * wv0;
                y1[j] += xv * wv1;
            }
        }
        __syncthreads();
    }
    #pragma unroll
    for (int j = 0; j < 4; j++) {
        y0[j] = y0[j] > 0.0f ? y0[j] : 0.0f;
        y1[j] = y1[j] > 0.0f ? y1[j] : 0.0f;
    }

    float p[4][5];
    #pragma unroll
    for (int c = 0; c < 5; c++) {
        float w0 = sWf[lane * 5 + c], w1 = sWf[(lane + 32) * 5 + c];
        #pragma unroll
        for (int j = 0; j < 4; j++)
            p[j][c] = y0[j] * w0 + y1[j] * w1;
    }
    #pragma unroll
    for (int o = 16; o > 0; o >>= 1) {
        #pragma unroll
        for (int j = 0; j < 4; j++)
            #pragma unroll
            for (int c = 0; c < 5; c++)
                p[j][c] += __shfl_xor_sync(0xffffffffu, p[j][c], o);
    }
    if (lane == 0) {
        #pragma unroll
        for (int j = 0; j < 4; j++)
            #pragma unroll
            for (int c = 0; c < 5; c++)
                out[(node0 + j) * 5 + c] = p[j][c] + bf[c];
    }
}

// ---------------- host: PDL launch helper --------------------------------------
static inline void launch_pdl(const void* func, dim3 grid, dim3 block, void** args) {
    cudaLaunchConfig_t cfg = {};
    cfg.gridDim = grid;
    cfg.blockDim = block;
    cfg.dynamicSmemBytes = 0;
    cfg.stream = 0;
    cudaLaunchAttribute attr[1];
    attr[0].id = cudaLaunchAttributeProgrammaticStreamSerialization;
    attr[0].val.programmaticStreamSerializationAllowed = 1;
    cfg.attrs = attr;
    cfg.numAttrs = 1;
    cudaLaunchKernelExC(&cfg, func, args);
}

// ---------------- host orchestration ------------------------------------------
extern "C" void kernel_launch(void* const* d_in, const int* in_sizes, int n_in,
                              void* d_out, int out_size) {
    const float* z     = (const float*)d_in[0];
    const int*   ei    = (const int*)d_in[1];
    const int*   batch = (const int*)d_in[2];
    int base = (in_sizes[3] == 1) ? 4 : 3;
    const float* W0  = (const float*)d_in[base + 0];
    const float* b0  = (const float*)d_in[base + 1];
    const float* W1  = (const float*)d_in[base + 2];
    const float* as1 = (const float*)d_in[base + 3];
    const float* ad1 = (const float*)d_in[base + 4];
    const float* bb1 = (const float*)d_in[base + 5];
    const float* W2  = (const float*)d_in[base + 6];
    const float* as2 = (const float*)d_in[base + 7];
    const float* ad2 = (const float*)d_in[base + 8];
    const float* bb2 = (const float*)d_in[base + 9];
    const float* W3  = (const float*)d_in[base + 10];
    const float* as3 = (const float*)d_in[base + 11];
    const float* ad3 = (const float*)d_in[base + 12];
    const float* bb3 = (const float*)d_in[base + 13];
    const float* Wg  = (const float*)d_in[base + 14];
    const float* bg  = (const float*)d_in[base + 15];
    const float* Wf  = (const float*)d_in[base + 16];
    const float* bf  = (const float*)d_in[base + 17];

    const int* srcArr = ei;
    const int* dstArr = ei + NEDGE;

    float *bufA, *bufB, *aS, *aD, *exB, *pgB, *maxB;
    int *startsB, *degB, *rowptrB, *cursorB, *csrcB;
    cudaGetSymbolAddress((void**)&bufA, g_bufA);
    cudaGetSymbolAddress((void**)&bufB, g_bufB);
    cudaGetSymbolAddress((void**)&aS, g_as);
    cudaGetSymbolAddress((void**)&aD, g_ad);
    cudaGetSymbolAddress((void**)&exB, g_ex);
    cudaGetSymbolAddress((void**)&pgB, g_pg);
    cudaGetSymbolAddress((void**)&maxB, g_maxS);
    cudaGetSymbolAddress((void**)&startsB, g_starts);
    cudaGetSymbolAddress((void**)&degB, g_deg);
    cudaGetSymbolAddress((void**)&rowptrB, g_rowptr);
    cudaGetSymbolAddress((void**)&cursorB, g_cursor);
    cudaGetSymbolAddress((void**)&csrcB, g_csrc);

    float* max0 = maxB;
    float* max1 = maxB + 4;
    float* max2 = maxB + 8;
    float* outP = (float*)d_out;

    {   // 1: prologue
        void* a[] = {&z, &W0, &b0, &W1, &pgB, &batch, &startsB, &degB, &dstArr};
        launch_pdl((const void*)k_pro, dim3(NGRAPH + NBLK + EBLK), dim3(256), a);
    }
    {   // 2: CSR rowptr + fill
        void* a[] = {&degB, &rowptrB, &cursorB, &csrcB, &maxB};
        launch_pdl((const void*)k_fill2, dim3(NBLK), dim3(256), a);
    }
    {   // 3: h1+attn | scatter | deg re-zero
        void* a[] = {&pgB, &W1, &batch, &startsB, &as1, &ad1, &bufB, &aS, &aD,
                     &srcArr, &dstArr, &cursorB, &csrcB, &degB, &max0};
        launch_pdl((const void*)k_mid, dim3(WBLK + EBLK + NBLK), dim3(256), a);
    }
    {   // 4: aggregate layer 1
        void* a[] = {&rowptrB, &csrcB, &bufB, &aS, &aD, &bb1, &max0, &exB, &bufA};
        launch_pdl((const void*)k_aggregate, dim3(WBLK), dim3(256), a);
    }
    {   // 5: layer-2 GEMM
        void* a[] = {&bufA, &W2, &as2, &ad2, &bufB, &aS, &aD, &max1};
        launch_pdl((const void*)k_gemm_attn, dim3(NNODE / 128, 2), dim3(256), a);
    }
    {   // 6: aggregate layer 2
        void* a[] = {&rowptrB, &csrcB, &bufB, &aS, &aD, &bb2, &max1, &exB, &bufA};
        launch_pdl((const void*)k_aggregate, dim3(WBLK), dim3(256), a);
    }
    {   // 7: layer-3 GEMM
        void* a[] = {&bufA, &W3, &as3, &ad3, &bufB, &aS, &aD, &max2};
        launch_pdl((const void*)k_gemm_attn, dim3(NNODE / 128, 2), dim3(256), a);
    }
    {   // 8: layer-3 aggregate fused with dec_geo + fc_geo (64 nodes/block)
        void* a[] = {&rowptrB, &csrcB, &bufB, &aS, &aD, &bb3, &max2, &exB,
                     &Wg, &bg, &Wf, &bf, &outP};
        launch_pdl((const void*)k_agg_final, dim3(AFBLK), dim3(512), a);
    }
}